// round 5
// baseline (speedup 1.0000x reference)
#include <cuda_runtime.h>
#include <math.h>

#define BB 8
#define SS 256
#define HH 100
#define PP 20
#define NP 21                 // 20 maxpool perspectives + 1 unweighted (cos)
#define EPSF 1e-8f
#define NTOK (BB*SS)
#define OD 105
#define NEGINF -3.0e38f
typedef unsigned long long ull;

// ---------------- scratch ----------------
__device__ float g_cp[NTOK*HH], g_ch[NTOK*HH];     // masked contexts [tok][h]
__device__ float g_cpT[BB*HH*SS], g_chT[BB*HH*SS]; // transposed [b][h][i]
__device__ float g_np[NTOK], g_nh[NTOK];
__device__ float g_wn[2][4][NTOK*PP];              // [side][full,maxpool,att,maxatt]
__device__ int   g_len[2][BB];
__device__ float g_last[2][BB*HH];
__device__ float g_cos[BB*SS*SS];
__device__ float g_rowsum[NTOK], g_colsum[NTOK];
__device__ float g_att_mean[2][NTOK*HH];
__device__ float g_att_max[2][NTOK*HH];
__device__ float g_psum[2][BB*NP*SS], g_pmax[2][BB*NP*SS];  // over-j partials, [jh]
__device__ float g_hsum[2][BB*NP*SS], g_hmax[2][BB*NP*SS];  // over-i partials, [ih]

// ---------------- K0: prep (mask, norms, weighted norms) + transpose, fused ------
__global__ void __launch_bounds__(256) k_prep(
    const float* __restrict__ ctx_p, const int* __restrict__ mask_p,
    const float* __restrict__ ctx_h, const int* __restrict__ mask_h,
    const float* __restrict__ w_full, const float* __restrict__ w_mp,
    const float* __restrict__ w_att, const float* __restrict__ w_ma)
{
    __shared__ float tile[32][101];
    int c0 = blockIdx.x * 32, b = blockIdx.y, side = blockIdx.z;
    const float* ctx = side ? ctx_h : ctx_p;
    const int* mask = side ? mask_h : mask_p;
    float* rowdst = side ? g_ch : g_cp;
    float* Tdst = (side ? g_chT : g_cpT) + b*HH*SS;
    int t = threadIdx.x;
    int base = b*SS + c0;

    for (int e = t; e < 32*HH; e += 256) {
        int i = e / HH, h = e - i*HH;
        float v = ctx[(base + i)*HH + h] * (float)mask[base + i];
        tile[i][h] = v;
        rowdst[(base + i)*HH + h] = v;
    }
    __syncthreads();

    // unweighted norms: warp wl handles tokens wl*4..wl*4+3
    int lane = t & 31, wl = t >> 5;
    for (int k = 0; k < 4; k++) {
        int i = wl*4 + k;
        float q = 0.f;
        for (int h = lane; h < HH; h += 32) { float v = tile[i][h]; q += v*v; }
        #pragma unroll
        for (int o = 16; o; o >>= 1) q += __shfl_xor_sync(0xffffffffu, q, o);
        if (lane == 0) (side ? g_nh : g_np)[base + i] = sqrtf(q);
    }

    // weighted norms: 80 (w,p) x 32 tokens = 2560 tasks
    const float* ws[4] = {w_full, w_mp, w_att, w_ma};
    for (int it = 0; it < 10; it++) {
        int task = t + 256*it;
        int wp = task >> 5, i = task & 31;
        int w = wp / PP, p = wp - w*PP;
        const float* wr = ws[w] + p*HH;
        float s = 0.f;
        #pragma unroll 4
        for (int h = 0; h < HH; h++) {
            float ww = wr[h]; float v = tile[i][h];
            s += ww*ww*v*v;
        }
        g_wn[side][w][(base + i)*PP + p] = sqrtf(s);
    }

    // transposed writes
    int i = t & 31, hb = t >> 5;
    for (int h = hb; h < HH; h += 8) Tdst[h*SS + c0 + i] = tile[i][h];
}

// ---------------- K0b: lengths + last token ---------------------------------------
__global__ void k_len_last(const int* __restrict__ mask_p, const int* __restrict__ mask_h)
{
    int w = threadIdx.x >> 5;
    int lane = threadIdx.x & 31;
    int side = w / BB, b = w % BB;
    const int* mask = side ? mask_h : mask_p;
    int s = 0;
    for (int j = lane; j < SS; j += 32) s += mask[b*SS + j];
    #pragma unroll
    for (int o = 16; o; o >>= 1) s += __shfl_xor_sync(0xffffffffu, s, o);
    if (lane == 0) g_len[side][b] = s;
    s = __shfl_sync(0xffffffffu, s, 0);
    int last = s > 0 ? s - 1 : 0;
    const float* src = (side ? g_ch : g_cp) + (b*SS + last)*HH;
    float* dst = g_last[side] + b*HH;
    for (int h = lane; h < HH; h += 32) dst[h] = src[h];
}

// ---------------- K1: unified GEMM + fused bidirectional reductions ---------------
// grid (4 = ih*2+jh, p=21, b=8). Block: 128 i x 128 j. Thread: 8x8 via f32x2.
__global__ void __launch_bounds__(256, 2) k_pw_all(const float* __restrict__ w_mp,
                                                   float* __restrict__ out)
{
    __shared__ float smem_buf[20*256 + 20*128];   // As2 | Bs ; reused for h-side stage
    __shared__ float n1s[128], n2s[128], wsq[128];
    float (*As2)[256] = (float(*)[256])smem_buf;          // duplicated pairs (a,a)
    float (*Bs)[128] = (float(*)[128])(smem_buf + 20*256);

    int ih = blockIdx.x >> 1, jh = blockIdx.x & 1;
    int p = blockIdx.y, b = blockIdx.z;
    int t = threadIdx.x, tx = t & 15, ty = t >> 4;

    if (t < 128) {
        int gi = b*SS + ih*128 + t;
        float n1 = (p < PP) ? g_wn[0][1][gi*PP + p] : g_np[gi];
        n1s[t] = 1.0f / fmaxf(n1, (p < PP) ? 1e-4f : EPSF);
        int gj = b*SS + jh*128 + t;
        float n2 = (p < PP) ? g_wn[1][1][gj*PP + p] : g_nh[gj];
        n2s[t] = 1.0f / fmaxf(n2, (p < PP) ? 1e-4f : EPSF);
    }
    if (t < HH) {
        if (p < PP) { float w = w_mp[p*HH + t]; wsq[t] = w*w; }
        else wsq[t] = 1.0f;
    }

    const float* gA = g_cpT + b*HH*SS + ih*128;
    const float* gB = g_chT + b*HH*SS + jh*128;

    ull acc[8][4];
    #pragma unroll
    for (int r = 0; r < 8; r++)
        #pragma unroll
        for (int c = 0; c < 4; c++) acc[r][c] = 0ull;

    float aReg[10], bReg[10];
    // prefetch chunk 0
    #pragma unroll
    for (int q = 0; q < 10; q++) {
        int e = t + 256*q;
        int kc = e >> 7, ii = e & 127;
        aReg[q] = gA[kc*SS + ii];
        bReg[q] = gB[kc*SS + ii];
    }

    for (int ch = 0; ch < 5; ch++) {
        __syncthreads();
        int k0 = ch*20;
        #pragma unroll
        for (int q = 0; q < 10; q++) {
            int e = t + 256*q;
            int kc = e >> 7, ii = e & 127;
            float av = wsq[k0 + kc] * aReg[q];
            float2 d; d.x = av; d.y = av;
            *(float2*)&As2[kc][ii*2] = d;
            Bs[kc][ii] = bReg[q];
        }
        __syncthreads();
        if (ch < 4) {
            int k0n = (ch + 1)*20;
            #pragma unroll
            for (int q = 0; q < 10; q++) {
                int e = t + 256*q;
                int kc = e >> 7, ii = e & 127;
                aReg[q] = gA[(k0n + kc)*SS + ii];
                bReg[q] = gB[(k0n + kc)*SS + ii];
            }
        }
        #pragma unroll
        for (int kc = 0; kc < 20; kc++) {
            const ulonglong2* bp = (const ulonglong2*)&Bs[kc][tx*8];
            ulonglong2 bv0 = bp[0], bv1 = bp[1];
            ull b2[4] = {bv0.x, bv0.y, bv1.x, bv1.y};
            const ulonglong2* ap = (const ulonglong2*)&As2[kc][ty*16];
            ulonglong2 av0 = ap[0], av1 = ap[1], av2 = ap[2], av3 = ap[3];
            ull a2[8] = {av0.x, av0.y, av1.x, av1.y, av2.x, av2.y, av3.x, av3.y};
            #pragma unroll
            for (int r = 0; r < 8; r++)
                #pragma unroll
                for (int c = 0; c < 4; c++)
                    asm("fma.rn.f32x2 %0, %1, %2, %0;"
                        : "+l"(acc[r][c]) : "l"(a2[r]), "l"(b2[c]));
        }
    }

    // ---------------- epilogue ----------------
    int lh = g_len[1][b], lp = g_len[0][b];
    float csum[8], cmax[8];
    #pragma unroll
    for (int k = 0; k < 8; k++) { csum[k] = 0.f; cmax[k] = NEGINF; }

    #pragma unroll
    for (int r = 0; r < 8; r++) {
        int iloc = ty*8 + r;
        int gi = b*SS + ih*128 + iloc;
        float n1i = n1s[iloc];
        float v[8];
        #pragma unroll
        for (int c = 0; c < 4; c++) {
            unsigned lo, hi;
            asm("mov.b64 {%0, %1}, %2;" : "=r"(lo), "=r"(hi) : "l"(acc[r][c]));
            v[2*c]   = __uint_as_float(lo) * n1i * n2s[tx*8 + 2*c];
            v[2*c+1] = __uint_as_float(hi) * n1i * n2s[tx*8 + 2*c + 1];
        }
        if (p == PP) {
            float4 s0 = make_float4(v[0], v[1], v[2], v[3]);
            float4 s1 = make_float4(v[4], v[5], v[6], v[7]);
            float* dst = g_cos + (size_t)gi*SS + jh*128 + tx*8;
            *(float4*)dst = s0;
            *(float4*)(dst + 4) = s1;
        }
        // over-j partial for this row
        float sm = 0.f, mx = NEGINF;
        #pragma unroll
        for (int k = 0; k < 8; k++) {
            sm += v[k];
            if (jh*128 + tx*8 + k < lh) mx = fmaxf(mx, v[k]);
        }
        #pragma unroll
        for (int o = 8; o; o >>= 1) {
            sm += __shfl_xor_sync(0xffffffffu, sm, o);
            mx = fmaxf(mx, __shfl_xor_sync(0xffffffffu, mx, o));
        }
        if (tx == 0) {
            int idx = (b*NP + p)*SS + ih*128 + iloc;
            g_psum[jh][idx] = sm;
            g_pmax[jh][idx] = mx;
        }
        // over-i accumulate
        bool valid = (ih*128 + iloc) < lp;
        #pragma unroll
        for (int k = 0; k < 8; k++) {
            csum[k] += v[k];
            if (valid) cmax[k] = fmaxf(cmax[k], v[k]);
        }
    }

    // stage over-i partials: reuse smem_buf
    __syncthreads();
    float* hsP = smem_buf;               // [16][136]
    float* hmP = smem_buf + 16*136;
    #pragma unroll
    for (int k = 0; k < 8; k++) {
        hsP[ty*136 + tx*8 + k] = csum[k];
        hmP[ty*136 + tx*8 + k] = cmax[k];
    }
    __syncthreads();
    if (t < 128) {
        float s = 0.f, m = NEGINF;
        #pragma unroll
        for (int y = 0; y < 16; y++) {
            s += hsP[y*136 + t];
            m = fmaxf(m, hmP[y*136 + t]);
        }
        int idx = (b*NP + p)*SS + jh*128 + t;
        g_hsum[ih][idx] = s;
        g_hmax[ih][idx] = m;
    }
}

// ---------------- K1b: combine halves, both directions ----------------------------
__global__ void k_comb(float* __restrict__ out)
{
    int bp = blockIdx.x;             // 0..167
    int b = bp / NP, p = bp % NP;
    int t = threadIdx.x;             // token index within b (i or j)
    int idx = bp*SS + t;
    int lh = g_len[1][b], lp = g_len[0][b];
    // over-j (p-side, rows of side 0)
    float sm = g_psum[0][idx] + g_psum[1][idx];
    float mx = fmaxf(g_pmax[0][idx], g_pmax[1][idx]);
    float* op = out + (size_t)(b*SS + t)*OD;
    // over-i (h-side, rows of side 1)
    float hs = g_hsum[0][idx] + g_hsum[1][idx];
    float hm = fmaxf(g_hmax[0][idx], g_hmax[1][idx]);
    float* oh = out + (size_t)(NTOK + b*SS + t)*OD;
    if (p < PP) {
        op[23 + p] = mx;  op[43 + p] = sm / (float)lh;
        oh[23 + p] = hm;  oh[43 + p] = hs / (float)lp;
    } else {
        g_rowsum[b*SS + t] = sm;
        op[0] = mx;  op[1] = sm / (float)lh;
        g_colsum[b*SS + t] = hs;
        oh[0] = hm;  oh[1] = hs / (float)lp;
    }
}

// ---------------- K3: attentive mean + max (both sides, split reduce-dim) ---------
__global__ void __launch_bounds__(256) k_att()
{
    int b = blockIdx.x, tl = blockIdx.y, side = blockIdx.z;
    __shared__ float cs[8][257];
    __shared__ float red_s[2][8][104], red_m[2][8][104];
    int t = threadIdx.x;
    if (side == 0) {
        for (int e = t; e < 8*SS; e += 256) {
            int il = e >> 8, j = e & 255;
            cs[il][j] = g_cos[(b*SS + tl*8 + il)*SS + j];
        }
    } else {
        for (int e = t; e < 8*SS; e += 256) {
            int il = e & 7, i = e >> 3;
            cs[il][i] = g_cos[(b*SS + i)*SS + tl*8 + il];
        }
    }
    __syncthreads();
    int g = t >> 7, h = t & 127;
    int len = side ? g_len[0][b] : g_len[1][b];
    const float* vec = side ? g_cp : g_ch;
    int jbeg = g*128, jend = min(len, jbeg + 128);
    float sm[8], mx[8];
    #pragma unroll
    for (int il = 0; il < 8; il++) { sm[il] = 0.f; mx[il] = NEGINF; }
    if (h < HH) {
        for (int j = jbeg; j < jend; j++) {
            float c = __ldg(&vec[(b*SS + j)*HH + h]);
            #pragma unroll
            for (int il = 0; il < 8; il++) {
                float f = cs[il][j] * c;
                sm[il] += f;
                mx[il] = fmaxf(mx[il], f);
            }
        }
        #pragma unroll
        for (int il = 0; il < 8; il++) {
            red_s[g][il][h] = sm[il];
            red_m[g][il][h] = mx[il];
        }
    }
    __syncthreads();
    if (g == 0 && h < HH) {
        #pragma unroll
        for (int il = 0; il < 8; il++) {
            float s = red_s[0][il][h] + red_s[1][il][h];
            float m = fmaxf(red_m[0][il][h], red_m[1][il][h]);
            int tok = b*SS + tl*8 + il;
            float denom = side ? g_colsum[tok] : g_rowsum[tok];
            g_att_mean[side][tok*HH + h] = s / fmaxf(denom, EPSF);
            g_att_max[side][tok*HH + h] = m;
        }
    }
}

// ---------------- K4: multi-perspective match -------------------------------------
__global__ void k_match(const float* __restrict__ w_full, const float* __restrict__ w_att,
                        const float* __restrict__ w_ma, float* __restrict__ out)
{
    int which = blockIdx.y;
    int side = blockIdx.z;
    int gw = blockIdx.x*8 + (threadIdx.x >> 5);
    int lane = threadIdx.x & 31;
    int b = gw / SS;

    const float* v1 = (side ? g_ch : g_cp) + gw*HH;
    const float* wn1;
    const float* v2;
    const float* w;
    int col;
    if (which == 0) {
        wn1 = g_wn[side][0]; v2 = g_last[side ^ 1] + b*HH; w = w_full; col = 2;
    } else if (which == 1) {
        wn1 = g_wn[side][2]; v2 = g_att_mean[side] + gw*HH; w = w_att; col = 63;
    } else {
        wn1 = g_wn[side][3]; v2 = g_att_max[side] + gw*HH; w = w_ma; col = 84;
    }
    float* o = out + ((size_t)side*NTOK + gw)*OD;

    float r1[4], r2[4];
    float d = 0.f, q1 = 0.f, q2 = 0.f;
    #pragma unroll
    for (int k = 0; k < 4; k++) {
        int h = k*32 + lane;
        float a = (h < HH) ? v1[h] : 0.f;
        float c = (h < HH) ? v2[h] : 0.f;
        r1[k] = a; r2[k] = c;
        d += a*c; q1 += a*a; q2 += c*c;
    }
    #pragma unroll
    for (int of = 16; of; of >>= 1) {
        d  += __shfl_xor_sync(0xffffffffu, d, of);
        q1 += __shfl_xor_sync(0xffffffffu, q1, of);
        q2 += __shfl_xor_sync(0xffffffffu, q2, of);
    }
    if (lane == 0)
        o[col] = d / (fmaxf(sqrtf(q1), EPSF) * fmaxf(sqrtf(q2), EPSF));

    for (int p = 0; p < PP; p++) {
        float s12 = 0.f, s22 = 0.f;
        #pragma unroll
        for (int k = 0; k < 4; k++) {
            int h = k*32 + lane;
            float ww = (h < HH) ? w[p*HH + h] : 0.f;
            float w2 = ww*ww;
            s12 += w2 * r1[k] * r2[k];
            s22 += w2 * r2[k] * r2[k];
        }
        #pragma unroll
        for (int of = 16; of; of >>= 1) {
            s12 += __shfl_xor_sync(0xffffffffu, s12, of);
            s22 += __shfl_xor_sync(0xffffffffu, s22, of);
        }
        if (lane == 0) {
            float n1 = wn1[gw*PP + p];
            o[col + 1 + p] = s12 / (fmaxf(n1, EPSF) * fmaxf(sqrtf(s22), EPSF));
        }
    }
}

// ---------------- launcher --------------------------------------------------------
extern "C" void kernel_launch(void* const* d_in, const int* in_sizes, int n_in,
                              void* d_out, int out_size)
{
    const float* ctx_p  = (const float*)d_in[0];
    const int*   mask_p = (const int*)  d_in[1];
    const float* ctx_h  = (const float*)d_in[2];
    const int*   mask_h = (const int*)  d_in[3];
    const float* w_full = (const float*)d_in[4];
    const float* w_mp   = (const float*)d_in[5];
    const float* w_att  = (const float*)d_in[6];
    const float* w_ma   = (const float*)d_in[7];
    float* out = (float*)d_out;

    k_prep<<<dim3(8, BB, 2), 256>>>(ctx_p, mask_p, ctx_h, mask_h,
                                    w_full, w_mp, w_att, w_ma);
    k_len_last<<<1, 512>>>(mask_p, mask_h);
    k_pw_all<<<dim3(4, NP, BB), 256>>>(w_mp, out);
    k_comb<<<BB*NP, 256>>>(out);
    k_att<<<dim3(BB, 32, 2), 256>>>();
    k_match<<<dim3(256, 3, 2), 256>>>(w_full, w_att, w_ma, out);
}

// round 8
// speedup vs baseline: 1.1345x; 1.1345x over previous
#include <cuda_runtime.h>
#include <cuda_bf16.h>
#include <math.h>
#include <stdint.h>

#define BB 8
#define SS 256
#define HH 100
#define PP 20
#define NP 21
#define EPSF 1e-8f
#define NTOK (BB*SS)
#define OD 105
#define NEGINF -3.0e38f

__device__ float g_cp[NTOK*HH], g_ch[NTOK*HH];
__device__ float g_np[NTOK], g_nh[NTOK];
__device__ float g_wn[2][4][NTOK*PP];
__device__ int   g_len[2][BB];
__device__ float g_last[2][BB*HH];
__device__ float g_cos[BB*SS*SS];
__device__ float g_rowsum[NTOK], g_colsum[NTOK];
__device__ float g_att_mean[2][NTOK*HH];
__device__ float g_att_max[2][NTOK*HH];
__device__ float g_psum[2][BB*NP*SS], g_pmax[2][BB*NP*SS];
__device__ float g_hsum[2][BB*NP*SS], g_hmax[2][BB*NP*SS];
// ch bf16 hi/lo tiles: [b*2+jh][hi/lo][128 rows x 60 words (120 bf16, 112 used)]
__device__ __align__(16) uint32_t g_bsplit[BB*2][2][128*60];

__device__ __forceinline__ uint32_t pack_split(float v0, float v1, uint32_t& lo_out) {
    __nv_bfloat16 h0 = __float2bfloat16(v0);
    __nv_bfloat16 l0 = __float2bfloat16(v0 - __bfloat162float(h0));
    __nv_bfloat16 h1 = __float2bfloat16(v1);
    __nv_bfloat16 l1 = __float2bfloat16(v1 - __bfloat162float(h1));
    lo_out = (uint32_t)__bfloat16_as_ushort(l0) | ((uint32_t)__bfloat16_as_ushort(l1) << 16);
    return (uint32_t)__bfloat16_as_ushort(h0) | ((uint32_t)__bfloat16_as_ushort(h1) << 16);
}

#define MMA16816(c, a, bb) \
    asm volatile("mma.sync.aligned.m16n8k16.row.col.f32.bf16.bf16.f32 " \
        "{%0,%1,%2,%3}, {%4,%5,%6,%7}, {%8,%9}, {%0,%1,%2,%3};" \
        : "+f"((c)[0]), "+f"((c)[1]), "+f"((c)[2]), "+f"((c)[3]) \
        : "r"((a)[0]), "r"((a)[1]), "r"((a)[2]), "r"((a)[3]), \
          "r"((bb)[0]), "r"((bb)[1]))

// ---- K0: masked ctx, norms, weighted norms; side1 emits split B tiles ------------
__global__ void __launch_bounds__(256) k_prep(
    const float* __restrict__ ctx_p, const int* __restrict__ mask_p,
    const float* __restrict__ ctx_h, const int* __restrict__ mask_h,
    const float* __restrict__ w_full, const float* __restrict__ w_mp,
    const float* __restrict__ w_att, const float* __restrict__ w_ma)
{
    __shared__ float tile[32][101];
    int c0 = blockIdx.x * 32, b = blockIdx.y, side = blockIdx.z;
    const float* ctx = side ? ctx_h : ctx_p;
    const int* mask = side ? mask_h : mask_p;
    float* rowdst = side ? g_ch : g_cp;
    int t = threadIdx.x;
    int base = b*SS + c0;

    for (int e = t; e < 32*HH; e += 256) {
        int i = e / HH, h = e - i*HH;
        float v = ctx[(base + i)*HH + h] * (float)mask[base + i];
        tile[i][h] = v;
        rowdst[(base + i)*HH + h] = v;
    }
    __syncthreads();

    int lane = t & 31, wl = t >> 5;
    for (int k = 0; k < 4; k++) {
        int i = wl*4 + k;
        float qq = 0.f;
        for (int h = lane; h < HH; h += 32) { float v = tile[i][h]; qq += v*v; }
        #pragma unroll
        for (int o = 16; o; o >>= 1) qq += __shfl_xor_sync(0xffffffffu, qq, o);
        if (lane == 0) (side ? g_nh : g_np)[base + i] = sqrtf(qq);
    }

    const float* ws[4] = {w_full, w_mp, w_att, w_ma};
    for (int it = 0; it < 10; it++) {
        int task = t + 256*it;
        int wp = task >> 5, i = task & 31;
        int w = wp / PP, p = wp - w*PP;
        const float* wr = ws[w] + p*HH;
        float s = 0.f;
        #pragma unroll 4
        for (int h = 0; h < HH; h++) { float ww = wr[h]; float v = tile[i][h]; s += ww*ww*v*v; }
        g_wn[side][w][(base + i)*PP + p] = sqrtf(s);
    }

    if (side == 1) {
        int half = c0 >> 7, r0 = c0 & 127;
        uint32_t* hiB = &g_bsplit[b*2 + half][0][0];
        uint32_t* loB = &g_bsplit[b*2 + half][1][0];
        for (int e = t; e < 32*60; e += 256) {
            int i = e / 60, c2 = e - (e/60)*60;
            float v0 = (2*c2 < HH) ? tile[i][2*c2] : 0.f;
            float v1 = (2*c2+1 < HH) ? tile[i][2*c2+1] : 0.f;
            uint32_t lo, hi = pack_split(v0, v1, lo);
            int wdx = (r0 + i)*60 + c2;
            hiB[wdx] = hi; loB[wdx] = lo;
        }
    }
}

// ---- K0b: lengths + last token ---------------------------------------------------
__global__ void k_len_last(const int* __restrict__ mask_p, const int* __restrict__ mask_h)
{
    int w = threadIdx.x >> 5, lane = threadIdx.x & 31;
    int side = w / BB, b = w % BB;
    const int* mask = side ? mask_h : mask_p;
    int s = 0;
    for (int j = lane; j < SS; j += 32) s += mask[b*SS + j];
    #pragma unroll
    for (int o = 16; o; o >>= 1) s += __shfl_xor_sync(0xffffffffu, s, o);
    if (lane == 0) g_len[side][b] = s;
    s = __shfl_sync(0xffffffffu, s, 0);
    int last = s > 0 ? s - 1 : 0;
    const float* src = (side ? g_ch : g_cp) + (b*SS + last)*HH;
    float* dst = g_last[side] + b*HH;
    for (int h = lane; h < HH; h += 32) dst[h] = src[h];
}

// ---- K1: mma.sync split-bf16 GEMM + in-register bidirectional reductions ---------
// grid (4 = ih*2+jh, 21, 8), 256 thr. Warp grid 2(i) x 4(j); warp tile 64x32.
#define SMEM_DYN (4*7680*4 + (4*128*2 + 2*128*2)*4)
__global__ void __launch_bounds__(256, 1) k_mma(const float* __restrict__ w_mp)
{
    extern __shared__ __align__(16) uint32_t dsm[];
    uint32_t* AhW = dsm;                     // 128x60 words
    uint32_t* AlW = dsm + 7680;
    uint32_t* BhW = dsm + 2*7680;
    uint32_t* BlW = dsm + 3*7680;
    float* sjred = (float*)(dsm + 4*7680);   // [4][128]
    float* mjred = sjred + 512;
    float* sired = mjred + 512;              // [2][128]
    float* mired = sired + 256;
    __shared__ float inv1s[128], inv2s[128], w2s[128];

    int ih = blockIdx.x >> 1, jh = blockIdx.x & 1;
    int p = blockIdx.y, b = blockIdx.z;
    int t = threadIdx.x;
    int w = t >> 5, lane = t & 31;
    int g = lane >> 2, q = lane & 3;
    int wi = w >> 2, wj = w & 3;

    if (t < 128) {                           // FIX: guard (was overflowing [128] arrays)
        int gi = b*SS + ih*128 + t;
        float n1 = (p < PP) ? g_wn[0][1][gi*PP + p] : g_np[gi];
        inv1s[t] = 1.0f / fmaxf(n1, (p < PP) ? 1e-4f : EPSF);
        int gj = b*SS + jh*128 + t;
        float n2 = (p < PP) ? g_wn[1][1][gj*PP + p] : g_nh[gj];
        inv2s[t] = 1.0f / fmaxf(n2, (p < PP) ? 1e-4f : EPSF);
        w2s[t] = (t < HH) ? ((p < PP) ? w_mp[p*HH + t]*w_mp[p*HH + t] : 1.0f) : 0.f;
    }
    __syncthreads();

    // B: straight copy (hi and lo contiguous in g_bsplit)
    {
        const float4* src = (const float4*)&g_bsplit[b*2 + jh][0][0];
        float4* dst = (float4*)BhW;
        #pragma unroll
        for (int e = t; e < 3840; e += 256) dst[e] = src[e];
    }
    // A: scale fp32 cp rows by w^2, split to hi/lo
    {
        const float* cpb = g_cp + (size_t)(b*SS + ih*128)*HH;
        #pragma unroll 2
        for (int e = t; e < 7680; e += 256) {
            int row = e / 60, c2 = e - row*60;
            const float* sr = cpb + row*HH;
            float v0 = (2*c2 < HH) ? w2s[2*c2]*sr[2*c2] : 0.f;
            float v1 = (2*c2+1 < HH) ? w2s[2*c2+1]*sr[2*c2+1] : 0.f;
            uint32_t lo, hi = pack_split(v0, v1, lo);
            AhW[e] = hi; AlW[e] = lo;
        }
    }
    __syncthreads();

    float acc[4][4][4];
    #pragma unroll
    for (int m = 0; m < 4; m++)
        #pragma unroll
        for (int n = 0; n < 4; n++)
            #pragma unroll
            for (int k = 0; k < 4; k++) acc[m][n][k] = 0.f;

    #pragma unroll
    for (int ks = 0; ks < 7; ks++) {
        int kw = ks*8 + q;
        uint32_t aH[4][4], aL[4][4], bH[4][2], bL[4][2];
        #pragma unroll
        for (int m = 0; m < 4; m++) {
            int R = wi*64 + m*16 + g;
            aH[m][0] = AhW[R*60 + kw];
            aH[m][1] = AhW[(R+8)*60 + kw];
            aH[m][2] = AhW[R*60 + kw + 4];
            aH[m][3] = AhW[(R+8)*60 + kw + 4];
            aL[m][0] = AlW[R*60 + kw];
            aL[m][1] = AlW[(R+8)*60 + kw];
            aL[m][2] = AlW[R*60 + kw + 4];
            aL[m][3] = AlW[(R+8)*60 + kw + 4];
        }
        #pragma unroll
        for (int n = 0; n < 4; n++) {
            int C = wj*32 + n*8 + g;
            bH[n][0] = BhW[C*60 + kw];
            bH[n][1] = BhW[C*60 + kw + 4];
            bL[n][0] = BlW[C*60 + kw];
            bL[n][1] = BlW[C*60 + kw + 4];
        }
        #pragma unroll
        for (int m = 0; m < 4; m++)
            #pragma unroll
            for (int n = 0; n < 4; n++) {
                MMA16816(acc[m][n], aH[m], bH[n]);
                MMA16816(acc[m][n], aH[m], bL[n]);
                MMA16816(acc[m][n], aL[m], bH[n]);
            }
    }

    // ---- epilogue: normalize + dual reductions ----
    int lh = g_len[1][b], lp = g_len[0][b];
    int lhl = min(max(lh - jh*128, 0), 128);
    int lpl = min(max(lp - ih*128, 0), 128);

    float i1a[4], i1b[4], i2a[4], i2b[4];
    #pragma unroll
    for (int m = 0; m < 4; m++) {
        i1a[m] = inv1s[wi*64 + m*16 + g];
        i1b[m] = inv1s[wi*64 + m*16 + g + 8];
    }
    #pragma unroll
    for (int n = 0; n < 4; n++) {
        i2a[n] = inv2s[wj*32 + n*8 + 2*q];
        i2b[n] = inv2s[wj*32 + n*8 + 2*q + 1];
    }

    float jsum[8], jmaxv[8], isum[8], imaxv[8];
    #pragma unroll
    for (int k = 0; k < 8; k++) { jsum[k] = 0.f; jmaxv[k] = NEGINF; isum[k] = 0.f; imaxv[k] = NEGINF; }

    #pragma unroll
    for (int m = 0; m < 4; m++) {
        int r0v = wi*64 + m*16 + g;
        bool rv0 = r0v < lpl, rv1 = (r0v + 8) < lpl;
        #pragma unroll
        for (int n = 0; n < 4; n++) {
            int c0 = wj*32 + n*8 + 2*q;
            bool cv0 = c0 < lhl, cv1 = (c0 + 1) < lhl;
            float v0 = acc[m][n][0]*i1a[m]*i2a[n];
            float v1 = acc[m][n][1]*i1a[m]*i2b[n];
            float v2 = acc[m][n][2]*i1b[m]*i2a[n];
            float v3 = acc[m][n][3]*i1b[m]*i2b[n];
            jsum[2*m] += v0 + v1;  jsum[2*m+1] += v2 + v3;
            if (cv0) { jmaxv[2*m] = fmaxf(jmaxv[2*m], v0); jmaxv[2*m+1] = fmaxf(jmaxv[2*m+1], v2); }
            if (cv1) { jmaxv[2*m] = fmaxf(jmaxv[2*m], v1); jmaxv[2*m+1] = fmaxf(jmaxv[2*m+1], v3); }
            isum[2*n] += v0 + v2;  isum[2*n+1] += v1 + v3;
            if (rv0) { imaxv[2*n] = fmaxf(imaxv[2*n], v0); imaxv[2*n+1] = fmaxf(imaxv[2*n+1], v1); }
            if (rv1) { imaxv[2*n] = fmaxf(imaxv[2*n], v2); imaxv[2*n+1] = fmaxf(imaxv[2*n+1], v3); }
            if (p == PP) {
                float* dst = g_cos + (size_t)(b*SS + ih*128 + r0v)*SS + jh*128 + c0;
                float2 s0; s0.x = v0; s0.y = v1;
                float2 s1; s1.x = v2; s1.y = v3;
                *(float2*)dst = s0;
                *(float2*)(dst + 8*SS) = s1;
            }
        }
    }

    #pragma unroll
    for (int k = 0; k < 8; k++) {
        #pragma unroll
        for (int off = 1; off <= 2; off <<= 1) {
            jsum[k] += __shfl_xor_sync(0xffffffffu, jsum[k], off);
            jmaxv[k] = fmaxf(jmaxv[k], __shfl_xor_sync(0xffffffffu, jmaxv[k], off));
        }
        #pragma unroll
        for (int off = 4; off <= 16; off <<= 1) {
            isum[k] += __shfl_xor_sync(0xffffffffu, isum[k], off);
            imaxv[k] = fmaxf(imaxv[k], __shfl_xor_sync(0xffffffffu, imaxv[k], off));
        }
    }
    if (q == 0) {
        #pragma unroll
        for (int m = 0; m < 4; m++) {
            #pragma unroll
            for (int hf = 0; hf < 2; hf++) {
                int row = wi*64 + m*16 + hf*8 + g;
                sjred[wj*128 + row] = jsum[2*m + hf];
                mjred[wj*128 + row] = jmaxv[2*m + hf];
            }
        }
    }
    if (g == 0) {
        #pragma unroll
        for (int n = 0; n < 4; n++) {
            int c0 = wj*32 + n*8 + 2*q;
            sired[wi*128 + c0] = isum[2*n];     sired[wi*128 + c0 + 1] = isum[2*n+1];
            mired[wi*128 + c0] = imaxv[2*n];    mired[wi*128 + c0 + 1] = imaxv[2*n+1];
        }
    }
    __syncthreads();
    if (t < 128) {
        float s = sjred[t] + sjred[128 + t] + sjred[256 + t] + sjred[384 + t];
        float m = fmaxf(fmaxf(mjred[t], mjred[128 + t]), fmaxf(mjred[256 + t], mjred[384 + t]));
        int idx = (b*NP + p)*SS + ih*128 + t;
        g_psum[jh][idx] = s;
        g_pmax[jh][idx] = m;
        float s2 = sired[t] + sired[128 + t];
        float m2 = fmaxf(mired[t], mired[128 + t]);
        int idx2 = (b*NP + p)*SS + jh*128 + t;
        g_hsum[ih][idx2] = s2;
        g_hmax[ih][idx2] = m2;
    }
}

// ---- K1b: combine halves -----------------------------------------------------------
__global__ void k_comb(float* __restrict__ out)
{
    int bp = blockIdx.x;
    int b = bp / NP, p = bp % NP;
    int t = threadIdx.x;
    int idx = bp*SS + t;
    int lh = g_len[1][b], lp = g_len[0][b];
    float sm = g_psum[0][idx] + g_psum[1][idx];
    float mx = fmaxf(g_pmax[0][idx], g_pmax[1][idx]);
    float* op = out + (size_t)(b*SS + t)*OD;
    float hs = g_hsum[0][idx] + g_hsum[1][idx];
    float hm = fmaxf(g_hmax[0][idx], g_hmax[1][idx]);
    float* oh = out + (size_t)(NTOK + b*SS + t)*OD;
    if (p < PP) {
        op[23 + p] = mx;  op[43 + p] = sm / (float)lh;
        oh[23 + p] = hm;  oh[43 + p] = hs / (float)lp;
    } else {
        g_rowsum[b*SS + t] = sm;
        op[0] = mx;  op[1] = sm / (float)lh;
        g_colsum[b*SS + t] = hs;
        oh[0] = hm;  oh[1] = hs / (float)lp;
    }
}

// ---- K3: attentive mean + max ------------------------------------------------------
__global__ void __launch_bounds__(256) k_att()
{
    int b = blockIdx.x, tl = blockIdx.y, side = blockIdx.z;
    __shared__ float cs[8][257];
    __shared__ float red_s[2][8][104], red_m[2][8][104];
    int t = threadIdx.x;
    if (side == 0) {
        for (int e = t; e < 8*SS; e += 256) {
            int il = e >> 8, j = e & 255;
            cs[il][j] = g_cos[(b*SS + tl*8 + il)*SS + j];
        }
    } else {
        for (int e = t; e < 8*SS; e += 256) {
            int il = e & 7, i = e >> 3;
            cs[il][i] = g_cos[(b*SS + i)*SS + tl*8 + il];
        }
    }
    __syncthreads();
    int g = t >> 7, h = t & 127;
    int len = side ? g_len[0][b] : g_len[1][b];
    const float* vec = side ? g_cp : g_ch;
    int jbeg = g*128, jend = min(len, jbeg + 128);
    float sm[8], mx[8];
    #pragma unroll
    for (int il = 0; il < 8; il++) { sm[il] = 0.f; mx[il] = NEGINF; }
    if (h < HH) {
        for (int j = jbeg; j < jend; j++) {
            float c = __ldg(&vec[(b*SS + j)*HH + h]);
            #pragma unroll
            for (int il = 0; il < 8; il++) {
                float f = cs[il][j] * c;
                sm[il] += f;
                mx[il] = fmaxf(mx[il], f);
            }
        }
        #pragma unroll
        for (int il = 0; il < 8; il++) { red_s[g][il][h] = sm[il]; red_m[g][il][h] = mx[il]; }
    }
    __syncthreads();
    if (g == 0 && h < HH) {
        #pragma unroll
        for (int il = 0; il < 8; il++) {
            float s = red_s[0][il][h] + red_s[1][il][h];
            float m = fmaxf(red_m[0][il][h], red_m[1][il][h]);
            int tok = b*SS + tl*8 + il;
            float denom = side ? g_colsum[tok] : g_rowsum[tok];
            g_att_mean[side][tok*HH + h] = s / fmaxf(denom, EPSF);
            g_att_max[side][tok*HH + h] = m;
        }
    }
}

// ---- K4: multi-perspective match ---------------------------------------------------
__global__ void k_match(const float* __restrict__ w_full, const float* __restrict__ w_att,
                        const float* __restrict__ w_ma, float* __restrict__ out)
{
    int which = blockIdx.y, side = blockIdx.z;
    int gw = blockIdx.x*8 + (threadIdx.x >> 5);
    int lane = threadIdx.x & 31;
    int b = gw / SS;

    const float* v1 = (side ? g_ch : g_cp) + gw*HH;
    const float *wn1, *v2, *w;
    int col;
    if (which == 0)      { wn1 = g_wn[side][0]; v2 = g_last[side ^ 1] + b*HH;   w = w_full; col = 2; }
    else if (which == 1) { wn1 = g_wn[side][2]; v2 = g_att_mean[side] + gw*HH;  w = w_att;  col = 63; }
    else                 { wn1 = g_wn[side][3]; v2 = g_att_max[side] + gw*HH;   w = w_ma;   col = 84; }
    float* o = out + ((size_t)side*NTOK + gw)*OD;

    float r1[4], r2[4];
    float d = 0.f, q1 = 0.f, q2 = 0.f;
    #pragma unroll
    for (int k = 0; k < 4; k++) {
        int h = k*32 + lane;
        float a = (h < HH) ? v1[h] : 0.f;
        float c = (h < HH) ? v2[h] : 0.f;
        r1[k] = a; r2[k] = c;
        d += a*c; q1 += a*a; q2 += c*c;
    }
    #pragma unroll
    for (int of = 16; of; of >>= 1) {
        d  += __shfl_xor_sync(0xffffffffu, d, of);
        q1 += __shfl_xor_sync(0xffffffffu, q1, of);
        q2 += __shfl_xor_sync(0xffffffffu, q2, of);
    }
    if (lane == 0)
        o[col] = d / (fmaxf(sqrtf(q1), EPSF) * fmaxf(sqrtf(q2), EPSF));

    for (int p = 0; p < PP; p++) {
        float s12 = 0.f, s22 = 0.f;
        #pragma unroll
        for (int k = 0; k < 4; k++) {
            int h = k*32 + lane;
            float ww = (h < HH) ? w[p*HH + h] : 0.f;
            float w2 = ww*ww;
            s12 += w2 * r1[k] * r2[k];
            s22 += w2 * r2[k] * r2[k];
        }
        #pragma unroll
        for (int of = 16; of; of >>= 1) {
            s12 += __shfl_xor_sync(0xffffffffu, s12, of);
            s22 += __shfl_xor_sync(0xffffffffu, s22, of);
        }
        if (lane == 0) {
            float n1 = wn1[gw*PP + p];
            o[col + 1 + p] = s12 / (fmaxf(n1, EPSF) * fmaxf(sqrtf(s22), EPSF));
        }
    }
}

// ---- launcher ----------------------------------------------------------------------
extern "C" void kernel_launch(void* const* d_in, const int* in_sizes, int n_in,
                              void* d_out, int out_size)
{
    const float* ctx_p  = (const float*)d_in[0];
    const int*   mask_p = (const int*)  d_in[1];
    const float* ctx_h  = (const float*)d_in[2];
    const int*   mask_h = (const int*)  d_in[3];
    const float* w_full = (const float*)d_in[4];
    const float* w_mp   = (const float*)d_in[5];
    const float* w_att  = (const float*)d_in[6];
    const float* w_ma   = (const float*)d_in[7];
    float* out = (float*)d_out;

    cudaFuncSetAttribute(k_mma, cudaFuncAttributeMaxDynamicSharedMemorySize, SMEM_DYN);

    k_prep<<<dim3(8, BB, 2), 256>>>(ctx_p, mask_p, ctx_h, mask_h, w_full, w_mp, w_att, w_ma);
    k_len_last<<<1, 512>>>(mask_p, mask_h);
    k_mma<<<dim3(4, NP, BB), 256, SMEM_DYN>>>(w_mp);
    k_comb<<<BB*NP, 256>>>(out);
    k_att<<<dim3(BB, 32, 2), 256>>>();
    k_match<<<dim3(256, 3, 2), 256>>>(w_full, w_att, w_ma, out);
}

// round 10
// speedup vs baseline: 1.1614x; 1.0237x over previous
#include <cuda_runtime.h>
#include <cuda_bf16.h>
#include <math.h>
#include <stdint.h>

#define BB 8
#define SS 256
#define HH 100
#define PP 20
#define NP 21
#define EPSF 1e-8f
#define NTOK (BB*SS)
#define OD 105
#define NEGINF -3.0e38f

__device__ float g_cp[NTOK*HH], g_ch[NTOK*HH];
__device__ float g_np[NTOK], g_nh[NTOK];
__device__ float g_wn[2][4][NTOK*PP];
__device__ int   g_len[2][BB];
__device__ float g_last[2][BB*HH];
__device__ float g_cos[BB*SS*SS];
__device__ float g_rowsum[NTOK], g_colsum[NTOK];
__device__ float g_psum[2][BB*NP*SS], g_pmax[2][BB*NP*SS];
__device__ float g_hsum[2][BB*NP*SS], g_hmax[2][BB*NP*SS];
// ch bf16 hi/lo tiles: [b*2+jh][hi/lo][128 rows x 60 words]
__device__ __align__(16) uint32_t g_bsplit[BB*2][2][128*60];
// pre-scaled, pre-split A tiles: [p][b][ih][hi/lo][128x60 words]
__device__ __align__(16) uint32_t g_asplit[NP][BB][2][2][128*60];

__device__ __forceinline__ uint32_t pack_split(float v0, float v1, uint32_t& lo_out) {
    __nv_bfloat16 h0 = __float2bfloat16(v0);
    __nv_bfloat16 l0 = __float2bfloat16(v0 - __bfloat162float(h0));
    __nv_bfloat16 h1 = __float2bfloat16(v1);
    __nv_bfloat16 l1 = __float2bfloat16(v1 - __bfloat162float(h1));
    lo_out = (uint32_t)__bfloat16_as_ushort(l0) | ((uint32_t)__bfloat16_as_ushort(l1) << 16);
    return (uint32_t)__bfloat16_as_ushort(h0) | ((uint32_t)__bfloat16_as_ushort(h1) << 16);
}

#define MMA16816(c, a, bb) \
    asm volatile("mma.sync.aligned.m16n8k16.row.col.f32.bf16.bf16.f32 " \
        "{%0,%1,%2,%3}, {%4,%5,%6,%7}, {%8,%9}, {%0,%1,%2,%3};" \
        : "+f"((c)[0]), "+f"((c)[1]), "+f"((c)[2]), "+f"((c)[3]) \
        : "r"((a)[0]), "r"((a)[1]), "r"((a)[2]), "r"((a)[3]), \
          "r"((bb)[0]), "r"((bb)[1]))

// ---- K0: masked ctx, norms, weighted norms; side1 emits split B tiles ------------
__global__ void __launch_bounds__(256) k_prep(
    const float* __restrict__ ctx_p, const int* __restrict__ mask_p,
    const float* __restrict__ ctx_h, const int* __restrict__ mask_h,
    const float* __restrict__ w_full, const float* __restrict__ w_mp,
    const float* __restrict__ w_att, const float* __restrict__ w_ma)
{
    __shared__ float tile[32][101];
    int c0 = blockIdx.x * 32, b = blockIdx.y, side = blockIdx.z;
    const float* ctx = side ? ctx_h : ctx_p;
    const int* mask = side ? mask_h : mask_p;
    float* rowdst = side ? g_ch : g_cp;
    int t = threadIdx.x;
    int base = b*SS + c0;

    for (int e = t; e < 32*HH; e += 256) {
        int i = e / HH, h = e - i*HH;
        float v = ctx[(base + i)*HH + h] * (float)mask[base + i];
        tile[i][h] = v;
        rowdst[(base + i)*HH + h] = v;
    }
    __syncthreads();

    int lane = t & 31, wl = t >> 5;
    for (int k = 0; k < 4; k++) {
        int i = wl*4 + k;
        float qq = 0.f;
        for (int h = lane; h < HH; h += 32) { float v = tile[i][h]; qq += v*v; }
        #pragma unroll
        for (int o = 16; o; o >>= 1) qq += __shfl_xor_sync(0xffffffffu, qq, o);
        if (lane == 0) (side ? g_nh : g_np)[base + i] = sqrtf(qq);
    }

    const float* ws[4] = {w_full, w_mp, w_att, w_ma};
    for (int it = 0; it < 10; it++) {
        int task = t + 256*it;
        int wp = task >> 5, i = task & 31;
        int w = wp / PP, p = wp - w*PP;
        const float* wr = ws[w] + p*HH;
        float s = 0.f;
        #pragma unroll 4
        for (int h = 0; h < HH; h++) { float ww = wr[h]; float v = tile[i][h]; s += ww*ww*v*v; }
        g_wn[side][w][(base + i)*PP + p] = sqrtf(s);
    }

    if (side == 1) {
        int half = c0 >> 7, r0 = c0 & 127;
        uint32_t* hiB = &g_bsplit[b*2 + half][0][0];
        uint32_t* loB = &g_bsplit[b*2 + half][1][0];
        for (int e = t; e < 32*60; e += 256) {
            int i = e / 60, c2 = e - (e/60)*60;
            float v0 = (2*c2 < HH) ? tile[i][2*c2] : 0.f;
            float v1 = (2*c2+1 < HH) ? tile[i][2*c2+1] : 0.f;
            uint32_t lo, hi = pack_split(v0, v1, lo);
            int wdx = (r0 + i)*60 + c2;
            hiB[wdx] = hi; loB[wdx] = lo;
        }
    }
}

// ---- K0b: lengths + last token ---------------------------------------------------
__global__ void k_len_last(const int* __restrict__ mask_p, const int* __restrict__ mask_h)
{
    int w = threadIdx.x >> 5, lane = threadIdx.x & 31;
    int side = w / BB, b = w % BB;
    const int* mask = side ? mask_h : mask_p;
    int s = 0;
    for (int j = lane; j < SS; j += 32) s += mask[b*SS + j];
    #pragma unroll
    for (int o = 16; o; o >>= 1) s += __shfl_xor_sync(0xffffffffu, s, o);
    if (lane == 0) g_len[side][b] = s;
    s = __shfl_sync(0xffffffffu, s, 0);
    int last = s > 0 ? s - 1 : 0;
    const float* src = (side ? g_ch : g_cp) + (b*SS + last)*HH;
    float* dst = g_last[side] + b*HH;
    for (int h = lane; h < HH; h += 32) dst[h] = src[h];
}

// ---- K0c: pre-scale + split A tiles for all 21 perspectives ----------------------
__global__ void __launch_bounds__(256) k_splitA(const float* __restrict__ w_mp)
{
    int ih = blockIdx.x, p = blockIdx.y, b = blockIdx.z;
    __shared__ float w2s[128];
    int t = threadIdx.x;
    if (t < 128)
        w2s[t] = (t < HH) ? ((p < PP) ? w_mp[p*HH + t]*w_mp[p*HH + t] : 1.0f) : 0.f;
    __syncthreads();
    const float* cpb = g_cp + (size_t)(b*SS + ih*128)*HH;
    uint32_t* hiA = &g_asplit[p][b][ih][0][0];
    uint32_t* loA = &g_asplit[p][b][ih][1][0];
    for (int e = t; e < 7680; e += 256) {
        int row = e / 60, c2 = e - row*60;
        const float* sr = cpb + row*HH;
        float v0 = (2*c2 < HH) ? w2s[2*c2]*sr[2*c2] : 0.f;
        float v1 = (2*c2+1 < HH) ? w2s[2*c2+1]*sr[2*c2+1] : 0.f;
        uint32_t lo, hi = pack_split(v0, v1, lo);
        hiA[e] = hi; loA[e] = lo;
    }
}

// ---- K1: mma.sync split-bf16 GEMM + in-register bidirectional reductions ---------
#define SMEM_DYN (4*7680*4 + (4*128*2 + 2*128*2)*4)
__global__ void __launch_bounds__(256, 1) k_mma()
{
    extern __shared__ __align__(16) uint32_t dsm[];
    uint32_t* AhW = dsm;                     // 128x60 words
    uint32_t* AlW = dsm + 7680;
    uint32_t* BhW = dsm + 2*7680;
    uint32_t* BlW = dsm + 3*7680;
    float* sjred = (float*)(dsm + 4*7680);   // [4][128]
    float* mjred = sjred + 512;
    float* sired = mjred + 512;              // [2][128]
    float* mired = sired + 256;
    __shared__ float inv1s[128], inv2s[128];

    int ih = blockIdx.x >> 1, jh = blockIdx.x & 1;
    int p = blockIdx.y, b = blockIdx.z;
    int t = threadIdx.x;
    int w = t >> 5, lane = t & 31;
    int g = lane >> 2, q = lane & 3;
    int wi = w >> 2, wj = w & 3;

    if (t < 128) {
        int gi = b*SS + ih*128 + t;
        float n1 = (p < PP) ? g_wn[0][1][gi*PP + p] : g_np[gi];
        inv1s[t] = 1.0f / fmaxf(n1, (p < PP) ? 1e-4f : EPSF);
        int gj = b*SS + jh*128 + t;
        float n2 = (p < PP) ? g_wn[1][1][gj*PP + p] : g_nh[gj];
        inv2s[t] = 1.0f / fmaxf(n2, (p < PP) ? 1e-4f : EPSF);
    }

    // A + B: pure float4 copies of pre-split tiles (hi|lo contiguous)
    {
        const float4* sa = (const float4*)&g_asplit[p][b][ih][0][0];
        float4* da = (float4*)AhW;
        #pragma unroll
        for (int e = t; e < 3840; e += 256) da[e] = sa[e];
        const float4* sb = (const float4*)&g_bsplit[b*2 + jh][0][0];
        float4* db = (float4*)BhW;
        #pragma unroll
        for (int e = t; e < 3840; e += 256) db[e] = sb[e];
    }
    __syncthreads();

    float acc[4][4][4];
    #pragma unroll
    for (int m = 0; m < 4; m++)
        #pragma unroll
        for (int n = 0; n < 4; n++)
            #pragma unroll
            for (int k = 0; k < 4; k++) acc[m][n][k] = 0.f;

    #pragma unroll
    for (int ks = 0; ks < 7; ks++) {
        int kw = ks*8 + q;
        uint32_t aH[4][4], aL[4][4], bH[4][2], bL[4][2];
        #pragma unroll
        for (int m = 0; m < 4; m++) {
            int R = wi*64 + m*16 + g;
            aH[m][0] = AhW[R*60 + kw];
            aH[m][1] = AhW[(R+8)*60 + kw];
            aH[m][2] = AhW[R*60 + kw + 4];
            aH[m][3] = AhW[(R+8)*60 + kw + 4];
            aL[m][0] = AlW[R*60 + kw];
            aL[m][1] = AlW[(R+8)*60 + kw];
            aL[m][2] = AlW[R*60 + kw + 4];
            aL[m][3] = AlW[(R+8)*60 + kw + 4];
        }
        #pragma unroll
        for (int n = 0; n < 4; n++) {
            int C = wj*32 + n*8 + g;
            bH[n][0] = BhW[C*60 + kw];
            bH[n][1] = BhW[C*60 + kw + 4];
            bL[n][0] = BlW[C*60 + kw];
            bL[n][1] = BlW[C*60 + kw + 4];
        }
        #pragma unroll
        for (int m = 0; m < 4; m++)
            #pragma unroll
            for (int n = 0; n < 4; n++) {
                MMA16816(acc[m][n], aH[m], bH[n]);
                MMA16816(acc[m][n], aH[m], bL[n]);
                MMA16816(acc[m][n], aL[m], bH[n]);
            }
    }

    // ---- epilogue: normalize + dual reductions ----
    int lh = g_len[1][b], lp = g_len[0][b];
    int lhl = min(max(lh - jh*128, 0), 128);
    int lpl = min(max(lp - ih*128, 0), 128);

    float i1a[4], i1b[4], i2a[4], i2b[4];
    #pragma unroll
    for (int m = 0; m < 4; m++) {
        i1a[m] = inv1s[wi*64 + m*16 + g];
        i1b[m] = inv1s[wi*64 + m*16 + g + 8];
    }
    #pragma unroll
    for (int n = 0; n < 4; n++) {
        i2a[n] = inv2s[wj*32 + n*8 + 2*q];
        i2b[n] = inv2s[wj*32 + n*8 + 2*q + 1];
    }

    float jsum[8], jmaxv[8], isum[8], imaxv[8];
    #pragma unroll
    for (int k = 0; k < 8; k++) { jsum[k] = 0.f; jmaxv[k] = NEGINF; isum[k] = 0.f; imaxv[k] = NEGINF; }

    #pragma unroll
    for (int m = 0; m < 4; m++) {
        int r0v = wi*64 + m*16 + g;
        bool rv0 = r0v < lpl, rv1 = (r0v + 8) < lpl;
        #pragma unroll
        for (int n = 0; n < 4; n++) {
            int c0 = wj*32 + n*8 + 2*q;
            bool cv0 = c0 < lhl, cv1 = (c0 + 1) < lhl;
            float v0 = acc[m][n][0]*i1a[m]*i2a[n];
            float v1 = acc[m][n][1]*i1a[m]*i2b[n];
            float v2 = acc[m][n][2]*i1b[m]*i2a[n];
            float v3 = acc[m][n][3]*i1b[m]*i2b[n];
            jsum[2*m] += v0 + v1;  jsum[2*m+1] += v2 + v3;
            if (cv0) { jmaxv[2*m] = fmaxf(jmaxv[2*m], v0); jmaxv[2*m+1] = fmaxf(jmaxv[2*m+1], v2); }
            if (cv1) { jmaxv[2*m] = fmaxf(jmaxv[2*m], v1); jmaxv[2*m+1] = fmaxf(jmaxv[2*m+1], v3); }
            isum[2*n] += v0 + v2;  isum[2*n+1] += v1 + v3;
            if (rv0) { imaxv[2*n] = fmaxf(imaxv[2*n], v0); imaxv[2*n+1] = fmaxf(imaxv[2*n+1], v1); }
            if (rv1) { imaxv[2*n] = fmaxf(imaxv[2*n], v2); imaxv[2*n+1] = fmaxf(imaxv[2*n+1], v3); }
            if (p == PP) {
                float* dst = g_cos + (size_t)(b*SS + ih*128 + r0v)*SS + jh*128 + c0;
                float2 s0; s0.x = v0; s0.y = v1;
                float2 s1; s1.x = v2; s1.y = v3;
                *(float2*)dst = s0;
                *(float2*)(dst + 8*SS) = s1;
            }
        }
    }

    #pragma unroll
    for (int k = 0; k < 8; k++) {
        #pragma unroll
        for (int off = 1; off <= 2; off <<= 1) {
            jsum[k] += __shfl_xor_sync(0xffffffffu, jsum[k], off);
            jmaxv[k] = fmaxf(jmaxv[k], __shfl_xor_sync(0xffffffffu, jmaxv[k], off));
        }
        #pragma unroll
        for (int off = 4; off <= 16; off <<= 1) {
            isum[k] += __shfl_xor_sync(0xffffffffu, isum[k], off);
            imaxv[k] = fmaxf(imaxv[k], __shfl_xor_sync(0xffffffffu, imaxv[k], off));
        }
    }
    if (q == 0) {
        #pragma unroll
        for (int m = 0; m < 4; m++) {
            #pragma unroll
            for (int hf = 0; hf < 2; hf++) {
                int row = wi*64 + m*16 + hf*8 + g;
                sjred[wj*128 + row] = jsum[2*m + hf];
                mjred[wj*128 + row] = jmaxv[2*m + hf];
            }
        }
    }
    if (g == 0) {
        #pragma unroll
        for (int n = 0; n < 4; n++) {
            int c0 = wj*32 + n*8 + 2*q;
            sired[wi*128 + c0] = isum[2*n];     sired[wi*128 + c0 + 1] = isum[2*n+1];
            mired[wi*128 + c0] = imaxv[2*n];    mired[wi*128 + c0 + 1] = imaxv[2*n+1];
        }
    }
    __syncthreads();
    if (t < 128) {
        float s = sjred[t] + sjred[128 + t] + sjred[256 + t] + sjred[384 + t];
        float m = fmaxf(fmaxf(mjred[t], mjred[128 + t]), fmaxf(mjred[256 + t], mjred[384 + t]));
        int idx = (b*NP + p)*SS + ih*128 + t;
        g_psum[jh][idx] = s;
        g_pmax[jh][idx] = m;
        float s2 = sired[t] + sired[128 + t];
        float m2 = fmaxf(mired[t], mired[128 + t]);
        int idx2 = (b*NP + p)*SS + jh*128 + t;
        g_hsum[ih][idx2] = s2;
        g_hmax[ih][idx2] = m2;
    }
}

// ---- K1b: combine halves -----------------------------------------------------------
__global__ void k_comb(float* __restrict__ out)
{
    int bp = blockIdx.x;
    int b = bp / NP, p = bp % NP;
    int t = threadIdx.x;
    int idx = bp*SS + t;
    int lh = g_len[1][b], lp = g_len[0][b];
    float sm = g_psum[0][idx] + g_psum[1][idx];
    float mx = fmaxf(g_pmax[0][idx], g_pmax[1][idx]);
    float* op = out + (size_t)(b*SS + t)*OD;
    float hs = g_hsum[0][idx] + g_hsum[1][idx];
    float hm = fmaxf(g_hmax[0][idx], g_hmax[1][idx]);
    float* oh = out + (size_t)(NTOK + b*SS + t)*OD;
    if (p < PP) {
        op[23 + p] = mx;  op[43 + p] = sm / (float)lh;
        oh[23 + p] = hm;  oh[43 + p] = hs / (float)lp;
    } else {
        g_rowsum[b*SS + t] = sm;
        op[0] = mx;  op[1] = sm / (float)lh;
        g_colsum[b*SS + t] = hs;
        oh[0] = hm;  oh[1] = hs / (float)lp;
    }
}

// ---- K3: attentive mean + max, with fused attentive/max-attentive matching --------
__global__ void __launch_bounds__(256) k_att(const float* __restrict__ w_att,
                                             const float* __restrict__ w_ma,
                                             float* __restrict__ out)
{
    int b = blockIdx.x, tl = blockIdx.y, side = blockIdx.z;
    __shared__ float cs[8][257];
    __shared__ float red_s[2][8][104], red_m[2][8][104];
    __shared__ float amean[8][104], amax[8][104];
    int t = threadIdx.x;
    if (side == 0) {
        for (int e = t; e < 8*SS; e += 256) {
            int il = e >> 8, j = e & 255;
            cs[il][j] = g_cos[(b*SS + tl*8 + il)*SS + j];
        }
    } else {
        for (int e = t; e < 8*SS; e += 256) {
            int il = e & 7, i = e >> 3;
            cs[il][i] = g_cos[(b*SS + i)*SS + tl*8 + il];
        }
    }
    __syncthreads();
    int g2 = t >> 7, h = t & 127;
    int len = side ? g_len[0][b] : g_len[1][b];
    const float* vec = side ? g_cp : g_ch;
    int jbeg = g2*128, jend = min(len, jbeg + 128);
    float sm[8], mx[8];
    #pragma unroll
    for (int il = 0; il < 8; il++) { sm[il] = 0.f; mx[il] = NEGINF; }
    if (h < HH) {
        for (int j = jbeg; j < jend; j++) {
            float c = __ldg(&vec[(b*SS + j)*HH + h]);
            #pragma unroll
            for (int il = 0; il < 8; il++) {
                float f = cs[il][j] * c;
                sm[il] += f;
                mx[il] = fmaxf(mx[il], f);
            }
        }
        #pragma unroll
        for (int il = 0; il < 8; il++) { red_s[g2][il][h] = sm[il]; red_m[g2][il][h] = mx[il]; }
    }
    __syncthreads();
    if (g2 == 0 && h < HH) {
        #pragma unroll
        for (int il = 0; il < 8; il++) {
            float s = red_s[0][il][h] + red_s[1][il][h];
            float m = fmaxf(red_m[0][il][h], red_m[1][il][h]);
            int tok = b*SS + tl*8 + il;
            float denom = side ? g_colsum[tok] : g_rowsum[tok];
            amean[il][h] = s / fmaxf(denom, EPSF);
            amax[il][h] = m;
        }
    }
    __syncthreads();

    // fused matching: warp wl handles token tl*8+wl, both att (mean) & maxatt (max)
    int wl = t >> 5, lane = t & 31;
    int tok = b*SS + tl*8 + wl;
    const float* v1g = (side ? g_ch : g_cp) + (size_t)tok*HH;
    float* o = out + ((size_t)side*NTOK + tok)*OD;

    float r1[4];
    float q1 = 0.f;
    #pragma unroll
    for (int k = 0; k < 4; k++) {
        int hh = k*32 + lane;
        r1[k] = (hh < HH) ? v1g[hh] : 0.f;
        q1 += r1[k]*r1[k];
    }
    #pragma unroll
    for (int of = 16; of; of >>= 1) q1 += __shfl_xor_sync(0xffffffffu, q1, of);

    #pragma unroll
    for (int which = 0; which < 2; which++) {
        const float* v2s = which ? &amax[wl][0] : &amean[wl][0];
        const float* w = which ? w_ma : w_att;
        const float* wn1 = g_wn[side][2 + which];
        int col = which ? 84 : 63;

        float r2[4];
        float d = 0.f, q2 = 0.f;
        #pragma unroll
        for (int k = 0; k < 4; k++) {
            int hh = k*32 + lane;
            float c = (hh < HH) ? v2s[hh] : 0.f;
            r2[k] = c;
            d += r1[k]*c; q2 += c*c;
        }
        #pragma unroll
        for (int of = 16; of; of >>= 1) {
            d  += __shfl_xor_sync(0xffffffffu, d, of);
            q2 += __shfl_xor_sync(0xffffffffu, q2, of);
        }
        if (lane == 0)
            o[col] = d / (fmaxf(sqrtf(q1), EPSF) * fmaxf(sqrtf(q2), EPSF));

        for (int p = 0; p < PP; p++) {
            float s12 = 0.f, s22 = 0.f;
            #pragma unroll
            for (int k = 0; k < 4; k++) {
                int hh = k*32 + lane;
                float ww = (hh < HH) ? w[p*HH + hh] : 0.f;
                float w2 = ww*ww;
                s12 += w2 * r1[k] * r2[k];
                s22 += w2 * r2[k] * r2[k];
            }
            #pragma unroll
            for (int of = 16; of; of >>= 1) {
                s12 += __shfl_xor_sync(0xffffffffu, s12, of);
                s22 += __shfl_xor_sync(0xffffffffu, s22, of);
            }
            if (lane == 0) {
                float n1 = wn1[tok*PP + p];
                o[col + 1 + p] = s12 / (fmaxf(n1, EPSF) * fmaxf(sqrtf(s22), EPSF));
            }
        }
    }
}

// ---- K4: full match only (vs last valid token) -------------------------------------
__global__ void k_match(const float* __restrict__ w_full, float* __restrict__ out)
{
    int side = blockIdx.z;
    int gw = blockIdx.x*8 + (threadIdx.x >> 5);
    int lane = threadIdx.x & 31;
    int b = gw / SS;

    const float* v1 = (side ? g_ch : g_cp) + gw*HH;
    const float* wn1 = g_wn[side][0];
    const float* v2 = g_last[side ^ 1] + b*HH;
    const float* w = w_full;
    int col = 2;
    float* o = out + ((size_t)side*NTOK + gw)*OD;

    float r1[4], r2[4];
    float d = 0.f, q1 = 0.f, q2 = 0.f;
    #pragma unroll
    for (int k = 0; k < 4; k++) {
        int h = k*32 + lane;
        float a = (h < HH) ? v1[h] : 0.f;
        float c = (h < HH) ? v2[h] : 0.f;
        r1[k] = a; r2[k] = c;
        d += a*c; q1 += a*a; q2 += c*c;
    }
    #pragma unroll
    for (int of = 16; of; of >>= 1) {
        d  += __shfl_xor_sync(0xffffffffu, d, of);
        q1 += __shfl_xor_sync(0xffffffffu, q1, of);
        q2 += __shfl_xor_sync(0xffffffffu, q2, of);
    }
    if (lane == 0)
        o[col] = d / (fmaxf(sqrtf(q1), EPSF) * fmaxf(sqrtf(q2), EPSF));

    for (int p = 0; p < PP; p++) {
        float s12 = 0.f, s22 = 0.f;
        #pragma unroll
        for (int k = 0; k < 4; k++) {
            int h = k*32 + lane;
            float ww = (h < HH) ? w[p*HH + h] : 0.f;
            float w2 = ww*ww;
            s12 += w2 * r1[k] * r2[k];
            s22 += w2 * r2[k] * r2[k];
        }
        #pragma unroll
        for (int of = 16; of; of >>= 1) {
            s12 += __shfl_xor_sync(0xffffffffu, s12, of);
            s22 += __shfl_xor_sync(0xffffffffu, s22, of);
        }
        if (lane == 0) {
            float n1 = wn1[gw*PP + p];
            o[col + 1 + p] = s12 / (fmaxf(n1, EPSF) * fmaxf(sqrtf(s22), EPSF));
        }
    }
}

// ---- launcher ----------------------------------------------------------------------
extern "C" void kernel_launch(void* const* d_in, const int* in_sizes, int n_in,
                              void* d_out, int out_size)
{
    const float* ctx_p  = (const float*)d_in[0];
    const int*   mask_p = (const int*)  d_in[1];
    const float* ctx_h  = (const float*)d_in[2];
    const int*   mask_h = (const int*)  d_in[3];
    const float* w_full = (const float*)d_in[4];
    const float* w_mp   = (const float*)d_in[5];
    const float* w_att  = (const float*)d_in[6];
    const float* w_ma   = (const float*)d_in[7];
    float* out = (float*)d_out;

    cudaFuncSetAttribute(k_mma, cudaFuncAttributeMaxDynamicSharedMemorySize, SMEM_DYN);

    k_prep<<<dim3(8, BB, 2), 256>>>(ctx_p, mask_p, ctx_h, mask_h, w_full, w_mp, w_att, w_ma);
    k_len_last<<<1, 512>>>(mask_p, mask_h);
    k_splitA<<<dim3(2, NP, BB), 256>>>(w_mp);
    k_mma<<<dim3(4, NP, BB), 256, SMEM_DYN>>>();
    k_comb<<<BB*NP, 256>>>(out);
    k_att<<<dim3(BB, 32, 2), 256>>>(w_att, w_ma, out);
    k_match<<<dim3(256, 1, 2), 256>>>(w_full, out);
}

// round 11
// speedup vs baseline: 1.2026x; 1.0355x over previous
#include <cuda_runtime.h>
#include <cuda_bf16.h>
#include <math.h>
#include <stdint.h>

#define BB 8
#define SS 256
#define HH 100
#define PP 20
#define NP 21
#define EPSF 1e-8f
#define NTOK (BB*SS)
#define OD 105
#define NEGINF -3.0e38f

__device__ float g_cp[NTOK*HH], g_ch[NTOK*HH];
__device__ float g_np[NTOK], g_nh[NTOK];
__device__ float g_wn[2][4][NTOK*PP];
__device__ int   g_len[2][BB];
__device__ float g_last[2][BB*HH];
__device__ float g_cos[BB*SS*SS];
__device__ float g_rowsum[NTOK], g_colsum[NTOK];
__device__ float g_psum[2][BB*NP*SS], g_pmax[2][BB*NP*SS];
__device__ float g_hsum[2][BB*NP*SS], g_hmax[2][BB*NP*SS];
// ch bf16 hi/lo tiles: [b*2+jh][hi/lo][128 rows x 60 words]
__device__ __align__(16) uint32_t g_bsplit[BB*2][2][128*60];
// pre-scaled, pre-split A tiles: [p][b][ih][hi/lo][128x60 words]
__device__ __align__(16) uint32_t g_asplit[NP][BB][2][2][128*60];

__device__ __forceinline__ uint32_t pack_split(float v0, float v1, uint32_t& lo_out) {
    __nv_bfloat16 h0 = __float2bfloat16(v0);
    __nv_bfloat16 l0 = __float2bfloat16(v0 - __bfloat162float(h0));
    __nv_bfloat16 h1 = __float2bfloat16(v1);
    __nv_bfloat16 l1 = __float2bfloat16(v1 - __bfloat162float(h1));
    lo_out = (uint32_t)__bfloat16_as_ushort(l0) | ((uint32_t)__bfloat16_as_ushort(l1) << 16);
    return (uint32_t)__bfloat16_as_ushort(h0) | ((uint32_t)__bfloat16_as_ushort(h1) << 16);
}

#define MMA16816(c, a, bb) \
    asm volatile("mma.sync.aligned.m16n8k16.row.col.f32.bf16.bf16.f32 " \
        "{%0,%1,%2,%3}, {%4,%5,%6,%7}, {%8,%9}, {%0,%1,%2,%3};" \
        : "+f"((c)[0]), "+f"((c)[1]), "+f"((c)[2]), "+f"((c)[3]) \
        : "r"((a)[0]), "r"((a)[1]), "r"((a)[2]), "r"((a)[3]), \
          "r"((bb)[0]), "r"((bb)[1]))

// ---- K0: masked ctx, norms, weighted norms; side1 emits split B tiles ------------
__global__ void __launch_bounds__(256) k_prep(
    const float* __restrict__ ctx_p, const int* __restrict__ mask_p,
    const float* __restrict__ ctx_h, const int* __restrict__ mask_h,
    const float* __restrict__ w_full, const float* __restrict__ w_mp,
    const float* __restrict__ w_att, const float* __restrict__ w_ma)
{
    __shared__ float tile[32][101];
    int c0 = blockIdx.x * 32, b = blockIdx.y, side = blockIdx.z;
    const float* ctx = side ? ctx_h : ctx_p;
    const int* mask = side ? mask_h : mask_p;
    float* rowdst = side ? g_ch : g_cp;
    int t = threadIdx.x;
    int base = b*SS + c0;

    for (int e = t; e < 32*HH; e += 256) {
        int i = e / HH, h = e - i*HH;
        float v = ctx[(base + i)*HH + h] * (float)mask[base + i];
        tile[i][h] = v;
        rowdst[(base + i)*HH + h] = v;
    }
    __syncthreads();

    int lane = t & 31, wl = t >> 5;
    for (int k = 0; k < 4; k++) {
        int i = wl*4 + k;
        float qq = 0.f;
        for (int h = lane; h < HH; h += 32) { float v = tile[i][h]; qq += v*v; }
        #pragma unroll
        for (int o = 16; o; o >>= 1) qq += __shfl_xor_sync(0xffffffffu, qq, o);
        if (lane == 0) (side ? g_nh : g_np)[base + i] = sqrtf(qq);
    }

    const float* ws[4] = {w_full, w_mp, w_att, w_ma};
    for (int it = 0; it < 10; it++) {
        int task = t + 256*it;
        int wp = task >> 5, i = task & 31;
        int w = wp / PP, p = wp - w*PP;
        const float* wr = ws[w] + p*HH;
        float s = 0.f;
        #pragma unroll 4
        for (int h = 0; h < HH; h++) { float ww = wr[h]; float v = tile[i][h]; s += ww*ww*v*v; }
        g_wn[side][w][(base + i)*PP + p] = sqrtf(s);
    }

    if (side == 1) {
        int half = c0 >> 7, r0 = c0 & 127;
        uint32_t* hiB = &g_bsplit[b*2 + half][0][0];
        uint32_t* loB = &g_bsplit[b*2 + half][1][0];
        for (int e = t; e < 32*60; e += 256) {
            int i = e / 60, c2 = e - (e/60)*60;
            float v0 = (2*c2 < HH) ? tile[i][2*c2] : 0.f;
            float v1 = (2*c2+1 < HH) ? tile[i][2*c2+1] : 0.f;
            uint32_t lo, hi = pack_split(v0, v1, lo);
            int wdx = (r0 + i)*60 + c2;
            hiB[wdx] = hi; loB[wdx] = lo;
        }
    }
}

// ---- K0b: lengths + last token ---------------------------------------------------
__global__ void k_len_last(const int* __restrict__ mask_p, const int* __restrict__ mask_h)
{
    int w = threadIdx.x >> 5, lane = threadIdx.x & 31;
    int side = w / BB, b = w % BB;
    const int* mask = side ? mask_h : mask_p;
    int s = 0;
    for (int j = lane; j < SS; j += 32) s += mask[b*SS + j];
    #pragma unroll
    for (int o = 16; o; o >>= 1) s += __shfl_xor_sync(0xffffffffu, s, o);
    if (lane == 0) g_len[side][b] = s;
    s = __shfl_sync(0xffffffffu, s, 0);
    int last = s > 0 ? s - 1 : 0;
    const float* src = (side ? g_ch : g_cp) + (b*SS + last)*HH;
    float* dst = g_last[side] + b*HH;
    for (int h = lane; h < HH; h += 32) dst[h] = src[h];
}

// ---- K0c: pre-scale + split A tiles for all 21 perspectives ----------------------
__global__ void __launch_bounds__(256) k_splitA(const float* __restrict__ w_mp)
{
    int ih = blockIdx.x, p = blockIdx.y, b = blockIdx.z;
    __shared__ float w2s[128];
    int t = threadIdx.x;
    if (t < 128)
        w2s[t] = (t < HH) ? ((p < PP) ? w_mp[p*HH + t]*w_mp[p*HH + t] : 1.0f) : 0.f;
    __syncthreads();
    const float* cpb = g_cp + (size_t)(b*SS + ih*128)*HH;
    uint32_t* hiA = &g_asplit[p][b][ih][0][0];
    uint32_t* loA = &g_asplit[p][b][ih][1][0];
    for (int e = t; e < 7680; e += 256) {
        int row = e / 60, c2 = e - row*60;
        const float* sr = cpb + row*HH;
        float v0 = (2*c2 < HH) ? w2s[2*c2]*sr[2*c2] : 0.f;
        float v1 = (2*c2+1 < HH) ? w2s[2*c2+1]*sr[2*c2+1] : 0.f;
        uint32_t lo, hi = pack_split(v0, v1, lo);
        hiA[e] = hi; loA[e] = lo;
    }
}

// ---- K1: mma.sync split-bf16 GEMM, 3-stage smem (66KB -> 2 CTAs/SM) --------------
#define SMEM_DYN ((2*7680 + 1536)*4)
__global__ void __launch_bounds__(256, 2) k_mma()
{
    extern __shared__ __align__(16) uint32_t dsm[];
    uint32_t* AW = dsm;                      // 128x60 words (one of Ah/Al)
    uint32_t* BW = dsm + 7680;               // 128x60 words (one of Bh/Bl)
    float* sjred = (float*)(dsm + 2*7680);   // [4][128]
    float* mjred = sjred + 512;
    float* sired = mjred + 512;              // [2][128]
    float* mired = sired + 256;
    __shared__ float inv1s[128], inv2s[128];

    int ih = blockIdx.x >> 1, jh = blockIdx.x & 1;
    int p = blockIdx.y, b = blockIdx.z;
    int t = threadIdx.x;
    int w = t >> 5, lane = t & 31;
    int g = lane >> 2, q = lane & 3;
    int wi = w >> 2, wj = w & 3;

    if (t < 128) {
        int gi = b*SS + ih*128 + t;
        float n1 = (p < PP) ? g_wn[0][1][gi*PP + p] : g_np[gi];
        inv1s[t] = 1.0f / fmaxf(n1, (p < PP) ? 1e-4f : EPSF);
        int gj = b*SS + jh*128 + t;
        float n2 = (p < PP) ? g_wn[1][1][gj*PP + p] : g_nh[gj];
        inv2s[t] = 1.0f / fmaxf(n2, (p < PP) ? 1e-4f : EPSF);
    }

    const float4* aHi = (const float4*)&g_asplit[p][b][ih][0][0];   // 1920 float4
    const float4* aLo = (const float4*)&g_asplit[p][b][ih][1][0];
    const float4* bHi = (const float4*)&g_bsplit[b*2 + jh][0][0];
    const float4* bLo = (const float4*)&g_bsplit[b*2 + jh][1][0];
    float4* dA = (float4*)AW;
    float4* dB = (float4*)BW;

    float acc[4][4][4];
    #pragma unroll
    for (int m = 0; m < 4; m++)
        #pragma unroll
        for (int n = 0; n < 4; n++)
            #pragma unroll
            for (int k = 0; k < 4; k++) acc[m][n][k] = 0.f;

    #define MMA_PASS() do { \
        _Pragma("unroll") \
        for (int ks = 0; ks < 7; ks++) { \
            int kw = ks*8 + q; \
            uint32_t aF[4][4], bF[4][2]; \
            _Pragma("unroll") \
            for (int m = 0; m < 4; m++) { \
                int R = wi*64 + m*16 + g; \
                aF[m][0] = AW[R*60 + kw]; \
                aF[m][1] = AW[(R+8)*60 + kw]; \
                aF[m][2] = AW[R*60 + kw + 4]; \
                aF[m][3] = AW[(R+8)*60 + kw + 4]; \
            } \
            _Pragma("unroll") \
            for (int n = 0; n < 4; n++) { \
                int C = wj*32 + n*8 + g; \
                bF[n][0] = BW[C*60 + kw]; \
                bF[n][1] = BW[C*60 + kw + 4]; \
            } \
            _Pragma("unroll") \
            for (int m = 0; m < 4; m++) \
                _Pragma("unroll") \
                for (int n = 0; n < 4; n++) \
                    MMA16816(acc[m][n], aF[m], bF[n]); \
        } \
    } while (0)

    // stage 1: Ah x Bl
    #pragma unroll
    for (int e = t; e < 1920; e += 256) { dA[e] = aHi[e]; dB[e] = bLo[e]; }
    __syncthreads();
    MMA_PASS();
    __syncthreads();
    // stage 2: Ah x Bh
    #pragma unroll
    for (int e = t; e < 1920; e += 256) dB[e] = bHi[e];
    __syncthreads();
    MMA_PASS();
    __syncthreads();
    // stage 3: Al x Bh
    #pragma unroll
    for (int e = t; e < 1920; e += 256) dA[e] = aLo[e];
    __syncthreads();
    MMA_PASS();

    // ---- epilogue: normalize + dual reductions ----
    int lh = g_len[1][b], lp = g_len[0][b];
    int lhl = min(max(lh - jh*128, 0), 128);
    int lpl = min(max(lp - ih*128, 0), 128);

    float i1a[4], i1b[4], i2a[4], i2b[4];
    #pragma unroll
    for (int m = 0; m < 4; m++) {
        i1a[m] = inv1s[wi*64 + m*16 + g];
        i1b[m] = inv1s[wi*64 + m*16 + g + 8];
    }
    #pragma unroll
    for (int n = 0; n < 4; n++) {
        i2a[n] = inv2s[wj*32 + n*8 + 2*q];
        i2b[n] = inv2s[wj*32 + n*8 + 2*q + 1];
    }

    float jsum[8], jmaxv[8], isum[8], imaxv[8];
    #pragma unroll
    for (int k = 0; k < 8; k++) { jsum[k] = 0.f; jmaxv[k] = NEGINF; isum[k] = 0.f; imaxv[k] = NEGINF; }

    #pragma unroll
    for (int m = 0; m < 4; m++) {
        int r0v = wi*64 + m*16 + g;
        bool rv0 = r0v < lpl, rv1 = (r0v + 8) < lpl;
        #pragma unroll
        for (int n = 0; n < 4; n++) {
            int c0 = wj*32 + n*8 + 2*q;
            bool cv0 = c0 < lhl, cv1 = (c0 + 1) < lhl;
            float v0 = acc[m][n][0]*i1a[m]*i2a[n];
            float v1 = acc[m][n][1]*i1a[m]*i2b[n];
            float v2 = acc[m][n][2]*i1b[m]*i2a[n];
            float v3 = acc[m][n][3]*i1b[m]*i2b[n];
            jsum[2*m] += v0 + v1;  jsum[2*m+1] += v2 + v3;
            if (cv0) { jmaxv[2*m] = fmaxf(jmaxv[2*m], v0); jmaxv[2*m+1] = fmaxf(jmaxv[2*m+1], v2); }
            if (cv1) { jmaxv[2*m] = fmaxf(jmaxv[2*m], v1); jmaxv[2*m+1] = fmaxf(jmaxv[2*m+1], v3); }
            isum[2*n] += v0 + v2;  isum[2*n+1] += v1 + v3;
            if (rv0) { imaxv[2*n] = fmaxf(imaxv[2*n], v0); imaxv[2*n+1] = fmaxf(imaxv[2*n+1], v1); }
            if (rv1) { imaxv[2*n] = fmaxf(imaxv[2*n], v2); imaxv[2*n+1] = fmaxf(imaxv[2*n+1], v3); }
            if (p == PP) {
                float* dst = g_cos + (size_t)(b*SS + ih*128 + r0v)*SS + jh*128 + c0;
                float2 s0; s0.x = v0; s0.y = v1;
                float2 s1; s1.x = v2; s1.y = v3;
                *(float2*)dst = s0;
                *(float2*)(dst + 8*SS) = s1;
            }
        }
    }

    #pragma unroll
    for (int k = 0; k < 8; k++) {
        #pragma unroll
        for (int off = 1; off <= 2; off <<= 1) {
            jsum[k] += __shfl_xor_sync(0xffffffffu, jsum[k], off);
            jmaxv[k] = fmaxf(jmaxv[k], __shfl_xor_sync(0xffffffffu, jmaxv[k], off));
        }
        #pragma unroll
        for (int off = 4; off <= 16; off <<= 1) {
            isum[k] += __shfl_xor_sync(0xffffffffu, isum[k], off);
            imaxv[k] = fmaxf(imaxv[k], __shfl_xor_sync(0xffffffffu, imaxv[k], off));
        }
    }
    if (q == 0) {
        #pragma unroll
        for (int m = 0; m < 4; m++) {
            #pragma unroll
            for (int hf = 0; hf < 2; hf++) {
                int row = wi*64 + m*16 + hf*8 + g;
                sjred[wj*128 + row] = jsum[2*m + hf];
                mjred[wj*128 + row] = jmaxv[2*m + hf];
            }
        }
    }
    if (g == 0) {
        #pragma unroll
        for (int n = 0; n < 4; n++) {
            int c0 = wj*32 + n*8 + 2*q;
            sired[wi*128 + c0] = isum[2*n];     sired[wi*128 + c0 + 1] = isum[2*n+1];
            mired[wi*128 + c0] = imaxv[2*n];    mired[wi*128 + c0 + 1] = imaxv[2*n+1];
        }
    }
    __syncthreads();
    if (t < 128) {
        float s = sjred[t] + sjred[128 + t] + sjred[256 + t] + sjred[384 + t];
        float m = fmaxf(fmaxf(mjred[t], mjred[128 + t]), fmaxf(mjred[256 + t], mjred[384 + t]));
        int idx = (b*NP + p)*SS + ih*128 + t;
        g_psum[jh][idx] = s;
        g_pmax[jh][idx] = m;
        float s2 = sired[t] + sired[128 + t];
        float m2 = fmaxf(mired[t], mired[128 + t]);
        int idx2 = (b*NP + p)*SS + jh*128 + t;
        g_hsum[ih][idx2] = s2;
        g_hmax[ih][idx2] = m2;
    }
}

// ---- K1b: combine halves -----------------------------------------------------------
__global__ void k_comb(float* __restrict__ out)
{
    int bp = blockIdx.x;
    int b = bp / NP, p = bp % NP;
    int t = threadIdx.x;
    int idx = bp*SS + t;
    int lh = g_len[1][b], lp = g_len[0][b];
    float sm = g_psum[0][idx] + g_psum[1][idx];
    float mx = fmaxf(g_pmax[0][idx], g_pmax[1][idx]);
    float* op = out + (size_t)(b*SS + t)*OD;
    float hs = g_hsum[0][idx] + g_hsum[1][idx];
    float hm = fmaxf(g_hmax[0][idx], g_hmax[1][idx]);
    float* oh = out + (size_t)(NTOK + b*SS + t)*OD;
    if (p < PP) {
        op[23 + p] = mx;  op[43 + p] = sm / (float)lh;
        oh[23 + p] = hm;  oh[43 + p] = hs / (float)lp;
    } else {
        g_rowsum[b*SS + t] = sm;
        op[0] = mx;  op[1] = sm / (float)lh;
        g_colsum[b*SS + t] = hs;
        oh[0] = hm;  oh[1] = hs / (float)lp;
    }
}

// ---- K3: attentive mean+max, with fused attentive / max-attentive / full matching -
__global__ void __launch_bounds__(256) k_att(const float* __restrict__ w_att,
                                             const float* __restrict__ w_ma,
                                             const float* __restrict__ w_full,
                                             float* __restrict__ out)
{
    int b = blockIdx.x, tl = blockIdx.y, side = blockIdx.z;
    __shared__ float cs[8][257];
    __shared__ float red_s[2][8][104], red_m[2][8][104];
    __shared__ float amean[8][104], amax[8][104], lastv[104];
    int t = threadIdx.x;
    if (side == 0) {
        for (int e = t; e < 8*SS; e += 256) {
            int il = e >> 8, j = e & 255;
            cs[il][j] = g_cos[(b*SS + tl*8 + il)*SS + j];
        }
    } else {
        for (int e = t; e < 8*SS; e += 256) {
            int il = e & 7, i = e >> 3;
            cs[il][i] = g_cos[(b*SS + i)*SS + tl*8 + il];
        }
    }
    if (t < HH) lastv[t] = g_last[side ^ 1][b*HH + t];
    __syncthreads();
    int g2 = t >> 7, h = t & 127;
    int len = side ? g_len[0][b] : g_len[1][b];
    const float* vec = side ? g_cp : g_ch;
    int jbeg = g2*128, jend = min(len, jbeg + 128);
    float sm[8], mx[8];
    #pragma unroll
    for (int il = 0; il < 8; il++) { sm[il] = 0.f; mx[il] = NEGINF; }
    if (h < HH) {
        for (int j = jbeg; j < jend; j++) {
            float c = __ldg(&vec[(b*SS + j)*HH + h]);
            #pragma unroll
            for (int il = 0; il < 8; il++) {
                float f = cs[il][j] * c;
                sm[il] += f;
                mx[il] = fmaxf(mx[il], f);
            }
        }
        #pragma unroll
        for (int il = 0; il < 8; il++) { red_s[g2][il][h] = sm[il]; red_m[g2][il][h] = mx[il]; }
    }
    __syncthreads();
    if (g2 == 0 && h < HH) {
        #pragma unroll
        for (int il = 0; il < 8; il++) {
            float s = red_s[0][il][h] + red_s[1][il][h];
            float m = fmaxf(red_m[0][il][h], red_m[1][il][h]);
            int tok = b*SS + tl*8 + il;
            float denom = side ? g_colsum[tok] : g_rowsum[tok];
            amean[il][h] = s / fmaxf(denom, EPSF);
            amax[il][h] = m;
        }
    }
    __syncthreads();

    // fused matching: warp wl = token tl*8+wl; which: 0=att, 1=maxatt, 2=full
    int wl = t >> 5, lane = t & 31;
    int tok = b*SS + tl*8 + wl;
    const float* v1g = (side ? g_ch : g_cp) + (size_t)tok*HH;
    float* o = out + ((size_t)side*NTOK + tok)*OD;

    float r1[4];
    float q1 = 0.f;
    #pragma unroll
    for (int k = 0; k < 4; k++) {
        int hh = k*32 + lane;
        r1[k] = (hh < HH) ? v1g[hh] : 0.f;
        q1 += r1[k]*r1[k];
    }
    #pragma unroll
    for (int of = 16; of; of >>= 1) q1 += __shfl_xor_sync(0xffffffffu, q1, of);

    #pragma unroll
    for (int which = 0; which < 3; which++) {
        const float* v2s = (which == 0) ? &amean[wl][0] : (which == 1) ? &amax[wl][0] : lastv;
        const float* w = (which == 0) ? w_att : (which == 1) ? w_ma : w_full;
        const float* wn1 = g_wn[side][(which == 2) ? 0 : (2 + which)];
        int col = (which == 0) ? 63 : (which == 1) ? 84 : 2;

        float r2[4];
        float d = 0.f, q2 = 0.f;
        #pragma unroll
        for (int k = 0; k < 4; k++) {
            int hh = k*32 + lane;
            float c = (hh < HH) ? v2s[hh] : 0.f;
            r2[k] = c;
            d += r1[k]*c; q2 += c*c;
        }
        #pragma unroll
        for (int of = 16; of; of >>= 1) {
            d  += __shfl_xor_sync(0xffffffffu, d, of);
            q2 += __shfl_xor_sync(0xffffffffu, q2, of);
        }
        if (lane == 0)
            o[col] = d / (fmaxf(sqrtf(q1), EPSF) * fmaxf(sqrtf(q2), EPSF));

        for (int p = 0; p < PP; p++) {
            float s12 = 0.f, s22 = 0.f;
            #pragma unroll
            for (int k = 0; k < 4; k++) {
                int hh = k*32 + lane;
                float ww = (hh < HH) ? w[p*HH + hh] : 0.f;
                float w2 = ww*ww;
                s12 += w2 * r1[k] * r2[k];
                s22 += w2 * r2[k] * r2[k];
            }
            #pragma unroll
            for (int of = 16; of; of >>= 1) {
                s12 += __shfl_xor_sync(0xffffffffu, s12, of);
                s22 += __shfl_xor_sync(0xffffffffu, s22, of);
            }
            if (lane == 0) {
                float n1 = wn1[tok*PP + p];
                o[col + 1 + p] = s12 / (fmaxf(n1, EPSF) * fmaxf(sqrtf(s22), EPSF));
            }
        }
    }
}

// ---- launcher ----------------------------------------------------------------------
extern "C" void kernel_launch(void* const* d_in, const int* in_sizes, int n_in,
                              void* d_out, int out_size)
{
    const float* ctx_p  = (const float*)d_in[0];
    const int*   mask_p = (const int*)  d_in[1];
    const float* ctx_h  = (const float*)d_in[2];
    const int*   mask_h = (const int*)  d_in[3];
    const float* w_full = (const float*)d_in[4];
    const float* w_mp   = (const float*)d_in[5];
    const float* w_att  = (const float*)d_in[6];
    const float* w_ma   = (const float*)d_in[7];
    float* out = (float*)d_out;

    cudaFuncSetAttribute(k_mma, cudaFuncAttributeMaxDynamicSharedMemorySize, SMEM_DYN);

    k_prep<<<dim3(8, BB, 2), 256>>>(ctx_p, mask_p, ctx_h, mask_h, w_full, w_mp, w_att, w_ma);
    k_len_last<<<1, 512>>>(mask_p, mask_h);
    k_splitA<<<dim3(2, NP, BB), 256>>>(w_mp);
    k_mma<<<dim3(4, NP, BB), 256, SMEM_DYN>>>();
    k_comb<<<BB*NP, 256>>>(out);
    k_att<<<dim3(BB, 32, 2), 256>>>(w_att, w_ma, w_full, out);
}

// round 12
// speedup vs baseline: 1.5262x; 1.2691x over previous
#include <cuda_runtime.h>
#include <cuda_bf16.h>
#include <math.h>
#include <stdint.h>

#define BB 8
#define SS 256
#define HH 100
#define PP 20
#define NP 21
#define EPSF 1e-8f
#define NTOK (BB*SS)
#define OD 105
#define NEGINF -3.0e38f

__device__ float g_cp[NTOK*HH], g_ch[NTOK*HH];
__device__ float g_np[NTOK], g_nh[NTOK];
__device__ float g_wn[2][4][NTOK*PP];
__device__ int   g_len[2][BB];
__device__ float g_last[2][BB*HH];
__device__ float g_cos[BB*SS*SS];
__device__ float g_psum[2][BB*NP*SS], g_pmax[2][BB*NP*SS];
__device__ float g_hsum[2][BB*NP*SS], g_hmax[2][BB*NP*SS];
__device__ __align__(16) uint32_t g_bsplit[BB*2][2][128*60];
__device__ __align__(16) uint32_t g_asplit[NP][BB][2][2][128*60];

__device__ __forceinline__ uint32_t smem_u32(const void* p) {
    uint32_t a;
    asm("{ .reg .u64 t; cvta.to.shared.u64 t, %1; cvt.u32.u64 %0, t; }" : "=r"(a) : "l"(p));
    return a;
}
__device__ __forceinline__ uint32_t pack_split(float v0, float v1, uint32_t& lo_out) {
    __nv_bfloat16 h0 = __float2bfloat16(v0);
    __nv_bfloat16 l0 = __float2bfloat16(v0 - __bfloat162float(h0));
    __nv_bfloat16 h1 = __float2bfloat16(v1);
    __nv_bfloat16 l1 = __float2bfloat16(v1 - __bfloat162float(h1));
    lo_out = (uint32_t)__bfloat16_as_ushort(l0) | ((uint32_t)__bfloat16_as_ushort(l1) << 16);
    return (uint32_t)__bfloat16_as_ushort(h0) | ((uint32_t)__bfloat16_as_ushort(h1) << 16);
}

#define MMA16816(c, a, bb) \
    asm volatile("mma.sync.aligned.m16n8k16.row.col.f32.bf16.bf16.f32 " \
        "{%0,%1,%2,%3}, {%4,%5,%6,%7}, {%8,%9}, {%0,%1,%2,%3};" \
        : "+f"((c)[0]), "+f"((c)[1]), "+f"((c)[2]), "+f"((c)[3]) \
        : "r"((a)[0]), "r"((a)[1]), "r"((a)[2]), "r"((a)[3]), \
          "r"((bb)[0]), "r"((bb)[1]))
#define LDSM4(r, a) \
    asm volatile("ldmatrix.sync.aligned.m8n8.x4.shared.b16 {%0,%1,%2,%3}, [%4];" \
        : "=r"((r)[0]), "=r"((r)[1]), "=r"((r)[2]), "=r"((r)[3]) : "r"(a))
#define LDSM2(r, a) \
    asm volatile("ldmatrix.sync.aligned.m8n8.x2.shared.b16 {%0,%1}, [%2];" \
        : "=r"((r)[0]), "=r"((r)[1]) : "r"(a))

// ---- K0: masked ctx, norms, weighted norms, len+last; side1 emits split B tiles --
__global__ void __launch_bounds__(256) k_prep(
    const float* __restrict__ ctx_p, const int* __restrict__ mask_p,
    const float* __restrict__ ctx_h, const int* __restrict__ mask_h,
    const float* __restrict__ w_full, const float* __restrict__ w_mp,
    const float* __restrict__ w_att, const float* __restrict__ w_ma)
{
    __shared__ float tile[32][101];
    __shared__ int slen;
    int c0 = blockIdx.x * 32, b = blockIdx.y, side = blockIdx.z;
    const float* ctx = side ? ctx_h : ctx_p;
    const int* mask = side ? mask_h : mask_p;
    float* rowdst = side ? g_ch : g_cp;
    int t = threadIdx.x;
    int base = b*SS + c0;
    if (t == 0) slen = 0;

    for (int e = t; e < 32*HH; e += 256) {
        int i = e / HH, h = e - i*HH;
        float v = ctx[(base + i)*HH + h] * (float)mask[base + i];
        tile[i][h] = v;
        rowdst[(base + i)*HH + h] = v;
    }
    __syncthreads();
    atomicAdd(&slen, mask[b*SS + t]);

    int lane = t & 31, wl = t >> 5;
    for (int k = 0; k < 4; k++) {
        int i = wl*4 + k;
        float qq = 0.f;
        for (int h = lane; h < HH; h += 32) { float v = tile[i][h]; qq += v*v; }
        #pragma unroll
        for (int o = 16; o; o >>= 1) qq += __shfl_xor_sync(0xffffffffu, qq, o);
        if (lane == 0) (side ? g_nh : g_np)[base + i] = sqrtf(qq);
    }

    const float* ws[4] = {w_full, w_mp, w_att, w_ma};
    for (int it = 0; it < 10; it++) {
        int task = t + 256*it;
        int wp = task >> 5, i = task & 31;
        int w = wp / PP, p = wp - w*PP;
        const float* wr = ws[w] + p*HH;
        float s = 0.f;
        #pragma unroll 4
        for (int h = 0; h < HH; h++) { float ww = wr[h]; float v = tile[i][h]; s += ww*ww*v*v; }
        g_wn[side][w][(base + i)*PP + p] = sqrtf(s);
    }

    if (side == 1) {
        int half = c0 >> 7, r0 = c0 & 127;
        uint32_t* hiB = &g_bsplit[b*2 + half][0][0];
        uint32_t* loB = &g_bsplit[b*2 + half][1][0];
        for (int e = t; e < 32*60; e += 256) {
            int i = e / 60, c2 = e - (e/60)*60;
            float v0 = (2*c2 < HH) ? tile[i][2*c2] : 0.f;
            float v1 = (2*c2+1 < HH) ? tile[i][2*c2+1] : 0.f;
            uint32_t lo, hi = pack_split(v0, v1, lo);
            int wdx = (r0 + i)*60 + c2;
            hiB[wdx] = hi; loB[wdx] = lo;
        }
    }

    __syncthreads();
    int len = slen;
    int last = len > 0 ? len - 1 : 0;
    if (c0 == 0 && t == 0) g_len[side][b] = len;
    if (last >= c0 && last < c0 + 32)
        for (int h = t; h < HH; h += 256)
            g_last[side][b*HH + h] = tile[last - c0][h];
}

// ---- K0c: pre-scale + split A tiles for all 21 perspectives ----------------------
__global__ void __launch_bounds__(256) k_splitA(const float* __restrict__ w_mp)
{
    int ih = blockIdx.x, p = blockIdx.y, b = blockIdx.z;
    __shared__ float w2s[128];
    int t = threadIdx.x;
    if (t < 128)
        w2s[t] = (t < HH) ? ((p < PP) ? w_mp[p*HH + t]*w_mp[p*HH + t] : 1.0f) : 0.f;
    __syncthreads();
    const float* cpb = g_cp + (size_t)(b*SS + ih*128)*HH;
    uint32_t* hiA = &g_asplit[p][b][ih][0][0];
    uint32_t* loA = &g_asplit[p][b][ih][1][0];
    for (int e = t; e < 7680; e += 256) {
        int row = e / 60, c2 = e - row*60;
        const float* sr = cpb + row*HH;
        float v0 = (2*c2 < HH) ? w2s[2*c2]*sr[2*c2] : 0.f;
        float v1 = (2*c2+1 < HH) ? w2s[2*c2+1]*sr[2*c2+1] : 0.f;
        uint32_t lo, hi = pack_split(v0, v1, lo);
        hiA[e] = hi; loA[e] = lo;
    }
}

// ---- K1: mma.sync split-bf16 GEMM, 3-stage smem, ldmatrix fragment loads ---------
#define SMEM_DYN ((2*7680 + 1536)*4)
__global__ void __launch_bounds__(256, 2) k_mma()
{
    extern __shared__ __align__(16) uint32_t dsm[];
    uint32_t* AW = dsm;                      // 128x60 words (one of Ah/Al)
    uint32_t* BW = dsm + 7680;
    float* sjred = (float*)(dsm + 2*7680);   // [4][128]
    float* mjred = sjred + 512;
    float* sired = mjred + 512;              // [2][128]
    float* mired = sired + 256;
    __shared__ float inv1s[128], inv2s[128];

    int ih = blockIdx.x >> 1, jh = blockIdx.x & 1;
    int p = blockIdx.y, b = blockIdx.z;
    int t = threadIdx.x;
    int w = t >> 5, lane = t & 31;
    int g = lane >> 2, q = lane & 3;
    int wi = w >> 2, wj = w & 3;

    if (t < 128) {
        int gi = b*SS + ih*128 + t;
        float n1 = (p < PP) ? g_wn[0][1][gi*PP + p] : g_np[gi];
        inv1s[t] = 1.0f / fmaxf(n1, (p < PP) ? 1e-4f : EPSF);
        int gj = b*SS + jh*128 + t;
        float n2 = (p < PP) ? g_wn[1][1][gj*PP + p] : g_nh[gj];
        inv2s[t] = 1.0f / fmaxf(n2, (p < PP) ? 1e-4f : EPSF);
    }

    // ldmatrix per-thread base addresses
    uint32_t aw0 = smem_u32(AW), bw0 = smem_u32(BW);
    uint32_t aAdr[4], bAdr[4];
    #pragma unroll
    for (int m = 0; m < 4; m++)
        aAdr[m] = aw0 + ((((wi*64 + m*16 + (lane & 15))*60) + (lane >> 4)*4) << 2);
    #pragma unroll
    for (int n = 0; n < 4; n++)
        bAdr[n] = bw0 + ((((wj*32 + n*8 + (lane & 7))*60) + ((lane >> 3) & 1)*4) << 2);

    const float4* aHi = (const float4*)&g_asplit[p][b][ih][0][0];
    const float4* aLo = (const float4*)&g_asplit[p][b][ih][1][0];
    const float4* bHi = (const float4*)&g_bsplit[b*2 + jh][0][0];
    const float4* bLo = (const float4*)&g_bsplit[b*2 + jh][1][0];
    float4* dA = (float4*)AW;
    float4* dB = (float4*)BW;

    float acc[4][4][4];
    #pragma unroll
    for (int m = 0; m < 4; m++)
        #pragma unroll
        for (int n = 0; n < 4; n++)
            #pragma unroll
            for (int k = 0; k < 4; k++) acc[m][n][k] = 0.f;

    #define MMA_PASS() do { \
        _Pragma("unroll") \
        for (int ks = 0; ks < 7; ks++) { \
            uint32_t aF[4][4], bF[4][2]; \
            _Pragma("unroll") \
            for (int m = 0; m < 4; m++) LDSM4(aF[m], aAdr[m] + ks*32); \
            _Pragma("unroll") \
            for (int n = 0; n < 4; n++) LDSM2(bF[n], bAdr[n] + ks*32); \
            _Pragma("unroll") \
            for (int m = 0; m < 4; m++) \
                _Pragma("unroll") \
                for (int n = 0; n < 4; n++) \
                    MMA16816(acc[m][n], aF[m], bF[n]); \
        } \
    } while (0)

    // stage 1: Ah x Bl
    #pragma unroll
    for (int e = t; e < 1920; e += 256) { dA[e] = aHi[e]; dB[e] = bLo[e]; }
    __syncthreads();
    MMA_PASS();
    __syncthreads();
    // stage 2: Ah x Bh
    #pragma unroll
    for (int e = t; e < 1920; e += 256) dB[e] = bHi[e];
    __syncthreads();
    MMA_PASS();
    __syncthreads();
    // stage 3: Al x Bh
    #pragma unroll
    for (int e = t; e < 1920; e += 256) dA[e] = aLo[e];
    __syncthreads();
    MMA_PASS();

    // ---- epilogue: normalize + dual reductions ----
    int lh = g_len[1][b], lp = g_len[0][b];
    int lhl = min(max(lh - jh*128, 0), 128);
    int lpl = min(max(lp - ih*128, 0), 128);

    float i1a[4], i1b[4], i2a[4], i2b[4];
    #pragma unroll
    for (int m = 0; m < 4; m++) {
        i1a[m] = inv1s[wi*64 + m*16 + g];
        i1b[m] = inv1s[wi*64 + m*16 + g + 8];
    }
    #pragma unroll
    for (int n = 0; n < 4; n++) {
        i2a[n] = inv2s[wj*32 + n*8 + 2*q];
        i2b[n] = inv2s[wj*32 + n*8 + 2*q + 1];
    }

    float jsum[8], jmaxv[8], isum[8], imaxv[8];
    #pragma unroll
    for (int k = 0; k < 8; k++) { jsum[k] = 0.f; jmaxv[k] = NEGINF; isum[k] = 0.f; imaxv[k] = NEGINF; }

    #pragma unroll
    for (int m = 0; m < 4; m++) {
        int r0v = wi*64 + m*16 + g;
        bool rv0 = r0v < lpl, rv1 = (r0v + 8) < lpl;
        #pragma unroll
        for (int n = 0; n < 4; n++) {
            int c0 = wj*32 + n*8 + 2*q;
            bool cv0 = c0 < lhl, cv1 = (c0 + 1) < lhl;
            float v0 = acc[m][n][0]*i1a[m]*i2a[n];
            float v1 = acc[m][n][1]*i1a[m]*i2b[n];
            float v2 = acc[m][n][2]*i1b[m]*i2a[n];
            float v3 = acc[m][n][3]*i1b[m]*i2b[n];
            jsum[2*m] += v0 + v1;  jsum[2*m+1] += v2 + v3;
            if (cv0) { jmaxv[2*m] = fmaxf(jmaxv[2*m], v0); jmaxv[2*m+1] = fmaxf(jmaxv[2*m+1], v2); }
            if (cv1) { jmaxv[2*m] = fmaxf(jmaxv[2*m], v1); jmaxv[2*m+1] = fmaxf(jmaxv[2*m+1], v3); }
            isum[2*n] += v0 + v2;  isum[2*n+1] += v1 + v3;
            if (rv0) { imaxv[2*n] = fmaxf(imaxv[2*n], v0); imaxv[2*n+1] = fmaxf(imaxv[2*n+1], v1); }
            if (rv1) { imaxv[2*n] = fmaxf(imaxv[2*n], v2); imaxv[2*n+1] = fmaxf(imaxv[2*n+1], v3); }
            if (p == PP) {
                float* dst = g_cos + (size_t)(b*SS + ih*128 + r0v)*SS + jh*128 + c0;
                float2 s0; s0.x = v0; s0.y = v1;
                float2 s1; s1.x = v2; s1.y = v3;
                *(float2*)dst = s0;
                *(float2*)(dst + 8*SS) = s1;
            }
        }
    }

    #pragma unroll
    for (int k = 0; k < 8; k++) {
        #pragma unroll
        for (int off = 1; off <= 2; off <<= 1) {
            jsum[k] += __shfl_xor_sync(0xffffffffu, jsum[k], off);
            jmaxv[k] = fmaxf(jmaxv[k], __shfl_xor_sync(0xffffffffu, jmaxv[k], off));
        }
        #pragma unroll
        for (int off = 4; off <= 16; off <<= 1) {
            isum[k] += __shfl_xor_sync(0xffffffffu, isum[k], off);
            imaxv[k] = fmaxf(imaxv[k], __shfl_xor_sync(0xffffffffu, imaxv[k], off));
        }
    }
    if (q == 0) {
        #pragma unroll
        for (int m = 0; m < 4; m++) {
            #pragma unroll
            for (int hf = 0; hf < 2; hf++) {
                int row = wi*64 + m*16 + hf*8 + g;
                sjred[wj*128 + row] = jsum[2*m + hf];
                mjred[wj*128 + row] = jmaxv[2*m + hf];
            }
        }
    }
    if (g == 0) {
        #pragma unroll
        for (int n = 0; n < 4; n++) {
            int c0 = wj*32 + n*8 + 2*q;
            sired[wi*128 + c0] = isum[2*n];     sired[wi*128 + c0 + 1] = isum[2*n+1];
            mired[wi*128 + c0] = imaxv[2*n];    mired[wi*128 + c0 + 1] = imaxv[2*n+1];
        }
    }
    __syncthreads();
    if (t < 128) {
        float s = sjred[t] + sjred[128 + t] + sjred[256 + t] + sjred[384 + t];
        float m = fmaxf(fmaxf(mjred[t], mjred[128 + t]), fmaxf(mjred[256 + t], mjred[384 + t]));
        int idx = (b*NP + p)*SS + ih*128 + t;
        g_psum[jh][idx] = s;
        g_pmax[jh][idx] = m;
        float s2 = sired[t] + sired[128 + t];
        float m2 = fmaxf(mired[t], mired[128 + t]);
        int idx2 = (b*NP + p)*SS + jh*128 + t;
        g_hsum[ih][idx2] = s2;
        g_hmax[ih][idx2] = m2;
    }
}

// ---- K3: comb + attentive mean/max + all three matchings (p-parallel) ------------
__global__ void __launch_bounds__(256) k_att(const float* __restrict__ w_att,
                                             const float* __restrict__ w_ma,
                                             const float* __restrict__ w_full,
                                             float* __restrict__ out)
{
    int b = blockIdx.x, tl = blockIdx.y, side = blockIdx.z;
    __shared__ float cs[8][257];             // reused as wsqc[20][101] in match phase
    __shared__ float red_s[2][8][104];       // reused as prod1/prod2 per warp
    __shared__ float red_m[2][8][104];
    __shared__ float amean[8][104], amax[8][104], lastv[104];
    __shared__ float rsum[8];
    int t = threadIdx.x;
    int dlen = side ? g_len[0][b] : g_len[1][b];

    // --- comb phase (fold of old k_comb for this block's 8 tokens) ---
    if (t < 168) {
        int il = t / 21, p = t - (t/21)*21;
        int tk = tl*8 + il;
        int idx = (b*NP + p)*SS + tk;
        float sm, mx;
        if (side == 0) {
            sm = g_psum[0][idx] + g_psum[1][idx];
            mx = fmaxf(g_pmax[0][idx], g_pmax[1][idx]);
        } else {
            sm = g_hsum[0][idx] + g_hsum[1][idx];
            mx = fmaxf(g_hmax[0][idx], g_hmax[1][idx]);
        }
        float* oo = out + ((size_t)side*NTOK + b*SS + tk)*OD;
        if (p < PP) { oo[23 + p] = mx; oo[43 + p] = sm / (float)dlen; }
        else        { oo[0] = mx;      oo[1] = sm / (float)dlen; rsum[il] = sm; }
    }
    if (t < 104) lastv[t] = (t < HH) ? g_last[side ^ 1][b*HH + t] : 0.f;

    // --- cos tile load ---
    if (side == 0) {
        for (int e = t; e < 8*SS; e += 256) {
            int il = e >> 8, j = e & 255;
            cs[il][j] = g_cos[(b*SS + tl*8 + il)*SS + j];
        }
    } else {
        for (int e = t; e < 8*SS; e += 256) {
            int il = e & 7, i = e >> 3;
            cs[il][i] = g_cos[(b*SS + i)*SS + tl*8 + il];
        }
    }
    __syncthreads();

    // --- attentive mean + max over reduce dim ---
    int g2 = t >> 7, h = t & 127;
    const float* vec = side ? g_cp : g_ch;
    int jbeg = g2*128, jend = min(dlen, jbeg + 128);
    float sm8[8], mx8[8];
    #pragma unroll
    for (int il = 0; il < 8; il++) { sm8[il] = 0.f; mx8[il] = NEGINF; }
    if (h < HH) {
        for (int j = jbeg; j < jend; j++) {
            float c = __ldg(&vec[(b*SS + j)*HH + h]);
            #pragma unroll
            for (int il = 0; il < 8; il++) {
                float f = cs[il][j] * c;
                sm8[il] += f;
                mx8[il] = fmaxf(mx8[il], f);
            }
        }
        #pragma unroll
        for (int il = 0; il < 8; il++) { red_s[g2][il][h] = sm8[il]; red_m[g2][il][h] = mx8[il]; }
    }
    __syncthreads();
    if (g2 == 0 && h < HH) {
        #pragma unroll
        for (int il = 0; il < 8; il++) {
            float s = red_s[0][il][h] + red_s[1][il][h];
            float m = fmaxf(red_m[0][il][h], red_m[1][il][h]);
            amean[il][h] = s / fmaxf(rsum[il], EPSF);
            amax[il][h] = m;
        }
    }

    // --- match phase: warp wl = token tl*8+wl; which: 0=att,1=maxatt,2=full ---
    int wl = t >> 5, lane = t & 31;
    int tok = b*SS + tl*8 + wl;
    const float* v1g = (side ? g_ch : g_cp) + (size_t)tok*HH;
    float* o = out + ((size_t)side*NTOK + tok)*OD;
    float* wsqc = &cs[0][0];                 // [20][101]
    float* prod1 = &red_s[0][wl][0];
    float* prod2 = &red_s[1][wl][0];

    float r1[4];
    float q1 = 0.f;
    #pragma unroll
    for (int k = 0; k < 4; k++) {
        int hh = k*32 + lane;
        r1[k] = (hh < HH) ? v1g[hh] : 0.f;
        q1 += r1[k]*r1[k];
    }
    #pragma unroll
    for (int of = 16; of; of >>= 1) q1 += __shfl_xor_sync(0xffffffffu, q1, of);

    const float* wlist[3] = {w_att, w_ma, w_full};
    #pragma unroll 1
    for (int which = 0; which < 3; which++) {
        __syncthreads();
        const float* wsrc = wlist[which];
        for (int e = t; e < 2020; e += 256) {
            int p = e / 101, hh = e - p*101;
            float wv = (hh < HH) ? wsrc[p*HH + hh] : 0.f;
            wsqc[e] = wv*wv;
        }
        __syncthreads();

        const float* v2s = (which == 0) ? &amean[wl][0] : (which == 1) ? &amax[wl][0] : lastv;
        const float* wn1 = g_wn[side][(which == 2) ? 0 : (2 + which)];
        int col = (which == 0) ? 63 : (which == 1) ? 84 : 2;

        float r2[4];
        float d = 0.f, q2 = 0.f;
        #pragma unroll
        for (int k = 0; k < 4; k++) {
            int hh = k*32 + lane;
            float c = (hh < HH) ? v2s[hh] : 0.f;
            r2[k] = c;
            d += r1[k]*c; q2 += c*c;
        }
        #pragma unroll
        for (int of = 16; of; of >>= 1) {
            d  += __shfl_xor_sync(0xffffffffu, d, of);
            q2 += __shfl_xor_sync(0xffffffffu, q2, of);
        }
        if (lane == 0)
            o[col] = d / (fmaxf(sqrtf(q1), EPSF) * fmaxf(sqrtf(q2), EPSF));

        #pragma unroll
        for (int k = 0; k < 4; k++) {
            int hh = k*32 + lane;
            if (hh < HH) { prod1[hh] = r1[k]*r2[k]; prod2[hh] = r2[k]*r2[k]; }
        }
        __syncwarp();
        if (lane < PP) {
            float s12 = 0.f, s22 = 0.f;
            const float* wr = wsqc + lane*101;
            #pragma unroll 4
            for (int hh = 0; hh < HH; hh++) {
                float wq = wr[hh];
                s12 += wq * prod1[hh];
                s22 += wq * prod2[hh];
            }
            float n1 = wn1[tok*PP + lane];
            o[col + 1 + lane] = s12 / (fmaxf(n1, EPSF) * fmaxf(sqrtf(s22), EPSF));
        }
        __syncwarp();
    }
}

// ---- launcher ----------------------------------------------------------------------
extern "C" void kernel_launch(void* const* d_in, const int* in_sizes, int n_in,
                              void* d_out, int out_size)
{
    const float* ctx_p  = (const float*)d_in[0];
    const int*   mask_p = (const int*)  d_in[1];
    const float* ctx_h  = (const float*)d_in[2];
    const int*   mask_h = (const int*)  d_in[3];
    const float* w_full = (const float*)d_in[4];
    const float* w_mp   = (const float*)d_in[5];
    const float* w_att  = (const float*)d_in[6];
    const float* w_ma   = (const float*)d_in[7];
    float* out = (float*)d_out;

    cudaFuncSetAttribute(k_mma, cudaFuncAttributeMaxDynamicSharedMemorySize, SMEM_DYN);

    k_prep<<<dim3(8, BB, 2), 256>>>(ctx_p, mask_p, ctx_h, mask_h, w_full, w_mp, w_att, w_ma);
    k_splitA<<<dim3(2, NP, BB), 256>>>(w_mp);
    k_mma<<<dim3(4, NP, BB), 256, SMEM_DYN>>>();
    k_att<<<dim3(BB, 32, 2), 256>>>(w_att, w_ma, w_full, out);
}